// round 1
// baseline (speedup 1.0000x reference)
#include <cuda_runtime.h>
#include <math.h>

#define NN 4096
#define DD 512
#define CC 128
#define ALPHA_ 0.0005f

typedef unsigned long long ull;

// Scratch (static device arrays — no allocations allowed)
__device__ float g_sq[NN];
__device__ ull   g_part[NN * 32 * 3];   // per-row, per-column-block partial top3
__device__ ull   g_top3[NN * 3];        // merged per-row top3 (sorted ascending)
__device__ float g_loss;
__device__ float g_reg;

// Insert key into sorted triple a0<=a1<=a2 (keep 3 smallest)
__device__ __forceinline__ void ins3(ull &a0, ull &a1, ull &a2, ull k) {
    if (k < a2) a2 = k;
    if (a2 < a1) { ull t = a1; a1 = a2; a2 = t; }
    if (a1 < a0) { ull t = a0; a0 = a1; a1 = t; }
}

__global__ void k_init() { g_loss = 0.f; g_reg = 0.f; }

// per-row squared norms of x
__global__ void k_sq(const float* __restrict__ x) {
    int row  = (blockIdx.x * blockDim.x + threadIdx.x) >> 5;
    int lane = threadIdx.x & 31;
    const float* xr = x + (size_t)row * DD;
    float s = 0.f;
    #pragma unroll
    for (int q = 0; q < DD / 32; ++q) { float v = xr[lane + 32 * q]; s = fmaf(v, v, s); }
    #pragma unroll
    for (int off = 16; off; off >>= 1) s += __shfl_down_sync(0xffffffffu, s, off);
    if (lane == 0) g_sq[row] = s;
}

// Tiled x @ x^T with fused per-row top-3 (on clamped d^2, stable tie-break by idx)
__global__ __launch_bounds__(256) void k_gemm_top3(const float* __restrict__ x) {
    __shared__ float As[32][132];
    __shared__ float Bs[32][132];
    int t  = threadIdx.x;
    int tx = t & 15, ty = t >> 4;
    int rowA = blockIdx.y * 128, rowB = blockIdx.x * 128;
    float acc[8][8];
    #pragma unroll
    for (int i = 0; i < 8; i++)
        #pragma unroll
        for (int j = 0; j < 8; j++) acc[i][j] = 0.f;

    for (int k0 = 0; k0 < DD; k0 += 32) {
        #pragma unroll
        for (int it = 0; it < 4; ++it) {
            int id = t + 256 * it;      // 0..1023 (128 rows x 8 float4)
            int r  = id >> 3;
            int kq = (id & 7) << 2;
            float4 va = *(const float4*)&x[(size_t)(rowA + r) * DD + k0 + kq];
            As[kq + 0][r] = va.x; As[kq + 1][r] = va.y; As[kq + 2][r] = va.z; As[kq + 3][r] = va.w;
            float4 vb = *(const float4*)&x[(size_t)(rowB + r) * DD + k0 + kq];
            Bs[kq + 0][r] = vb.x; Bs[kq + 1][r] = vb.y; Bs[kq + 2][r] = vb.z; Bs[kq + 3][r] = vb.w;
        }
        __syncthreads();
        #pragma unroll
        for (int kk = 0; kk < 32; ++kk) {
            float4 a0 = *(const float4*)&As[kk][ty * 8];
            float4 a1 = *(const float4*)&As[kk][ty * 8 + 4];
            float4 b0 = *(const float4*)&Bs[kk][tx * 8];
            float4 b1 = *(const float4*)&Bs[kk][tx * 8 + 4];
            float a[8] = {a0.x, a0.y, a0.z, a0.w, a1.x, a1.y, a1.z, a1.w};
            float b[8] = {b0.x, b0.y, b0.z, b0.w, b1.x, b1.y, b1.z, b1.w};
            #pragma unroll
            for (int i = 0; i < 8; i++)
                #pragma unroll
                for (int j = 0; j < 8; j++)
                    acc[i][j] = fmaf(a[i], b[j], acc[i][j]);
        }
        __syncthreads();
    }

    // Epilogue: d2 = sq_i + sq_j - 2*dot, clamp to 0, pack (d2bits<<32)|col, top-3 per row
    float sqa[8], sqb[8];
    #pragma unroll
    for (int i = 0; i < 8; i++) sqa[i] = g_sq[rowA + ty * 8 + i];
    #pragma unroll
    for (int j = 0; j < 8; j++) sqb[j] = g_sq[rowB + tx * 8 + j];

    #pragma unroll
    for (int mi = 0; mi < 8; ++mi) {
        ull t0 = ~0ull, t1 = ~0ull, t2 = ~0ull;
        #pragma unroll
        for (int ni = 0; ni < 8; ++ni) {
            float d2 = sqa[mi] + sqb[ni] - 2.f * acc[mi][ni];
            float e2 = d2 > 0.f ? d2 : 0.f;
            ull key = ((ull)__float_as_uint(e2) << 32) | (unsigned)(rowB + tx * 8 + ni);
            ins3(t0, t1, t2, key);
        }
        // reduce over the 16 tx-lanes that own this row (width-16 groups)
        #pragma unroll
        for (int off = 8; off; off >>= 1) {
            ull r0 = __shfl_down_sync(0xffffffffu, t0, off, 16);
            ull r1 = __shfl_down_sync(0xffffffffu, t1, off, 16);
            ull r2 = __shfl_down_sync(0xffffffffu, t2, off, 16);
            ins3(t0, t1, t2, r0); ins3(t0, t1, t2, r1); ins3(t0, t1, t2, r2);
        }
        if (tx == 0) {
            size_t base = ((size_t)(rowA + ty * 8 + mi) * 32 + blockIdx.x) * 3;
            g_part[base + 0] = t0; g_part[base + 1] = t1; g_part[base + 2] = t2;
        }
    }
}

// Merge 32 partial top-3 lists per row -> global top-3
__global__ void k_merge() {
    int row  = (blockIdx.x * blockDim.x + threadIdx.x) >> 5;
    int lane = threadIdx.x & 31;
    ull t0 = ~0ull, t1 = ~0ull, t2 = ~0ull;
    size_t base = (size_t)row * 96;
    for (int p = lane; p < 96; p += 32) ins3(t0, t1, t2, g_part[base + p]);
    #pragma unroll
    for (int off = 16; off; off >>= 1) {
        ull r0 = __shfl_down_sync(0xffffffffu, t0, off);
        ull r1 = __shfl_down_sync(0xffffffffu, t1, off);
        ull r2 = __shfl_down_sync(0xffffffffu, t2, off);
        ins3(t0, t1, t2, r0); ins3(t0, t1, t2, r1); ins3(t0, t1, t2, r2);
    }
    if (lane == 0) {
        g_top3[(size_t)row * 3 + 0] = t0;
        g_top3[(size_t)row * 3 + 1] = t1;
        g_top3[(size_t)row * 3 + 2] = t2;
    }
}

// Cross-entropy loss: logits = x@W + b, -mean(log_softmax[label])
__global__ __launch_bounds__(128) void k_loss(const float* __restrict__ x,
                                              const int* __restrict__ y,
                                              const float* __restrict__ W,
                                              const float* __restrict__ b) {
    __shared__ float xs[16][512];
    __shared__ float lg[16][128];
    int tid  = threadIdx.x;
    int row0 = blockIdx.x * 16;

    #pragma unroll
    for (int i = 0; i < 16; ++i) {
        int id = tid + 128 * i;      // 2048 float4 = 16 rows x 128 float4
        int r  = id >> 7;
        int q  = id & 127;
        float4 v = *(const float4*)&x[(size_t)(row0 + r) * DD + q * 4];
        *(float4*)&xs[r][q * 4] = v;
    }
    __syncthreads();

    float acc[16];
    #pragma unroll
    for (int r = 0; r < 16; r++) acc[r] = 0.f;
    int c = tid;
    for (int d0 = 0; d0 < DD; d0 += 4) {
        float w0 = W[(d0 + 0) * CC + c];
        float w1 = W[(d0 + 1) * CC + c];
        float w2 = W[(d0 + 2) * CC + c];
        float w3 = W[(d0 + 3) * CC + c];
        #pragma unroll
        for (int r = 0; r < 16; r++) {
            float4 xv = *(const float4*)&xs[r][d0];
            acc[r] += xv.x * w0 + xv.y * w1 + xv.z * w2 + xv.w * w3;
        }
    }
    float bc = b[c];
    #pragma unroll
    for (int r = 0; r < 16; r++) lg[r][c] = acc[r] + bc;
    __syncthreads();

    int w = tid >> 5, lane = tid & 31;
    for (int s = 0; s < 4; ++s) {
        int r = w * 4 + s;
        float l0 = lg[r][lane], l1 = lg[r][lane + 32], l2 = lg[r][lane + 64], l3 = lg[r][lane + 96];
        float mx = fmaxf(fmaxf(l0, l1), fmaxf(l2, l3));
        #pragma unroll
        for (int off = 16; off; off >>= 1) mx = fmaxf(mx, __shfl_xor_sync(0xffffffffu, mx, off));
        float se = expf(l0 - mx) + expf(l1 - mx) + expf(l2 - mx) + expf(l3 - mx);
        #pragma unroll
        for (int off = 16; off; off >>= 1) se += __shfl_xor_sync(0xffffffffu, se, off);
        if (lane == 0) {
            int lab  = y[row0 + r];
            float ll = lg[r][lab];
            atomicAdd(&g_loss, (mx + logf(se) - ll) * (1.0f / NN));
        }
    }
}

// reg = sum over rows i, neighbors n in top3(i), y[n]==y[i]:
//       dy(i,n) * exp(-d_sorted[i, n])  — only rank positions n<3 are non-negligible
__global__ void k_reg(const int* __restrict__ y, const float* __restrict__ yo) {
    int row  = (blockIdx.x * blockDim.x + threadIdx.x) >> 5;
    int lane = threadIdx.x & 31;
    ull k0 = g_top3[(size_t)row * 3 + 0];
    ull k1 = g_top3[(size_t)row * 3 + 1];
    ull k2 = g_top3[(size_t)row * 3 + 2];
    int yi = y[row];
    float acc = 0.f;
    #pragma unroll
    for (int t = 0; t < 3; ++t) {
        ull kt = (t == 0) ? k0 : (t == 1) ? k1 : k2;
        int n = (int)(kt & 0xffffffffu);
        // rank position = n; d_sorted[i,n] only known (and only relevant) for n in {0,1,2}
        float e2;
        bool use = true;
        if      (n == 0) e2 = __uint_as_float((unsigned)(k0 >> 32));
        else if (n == 1) e2 = __uint_as_float((unsigned)(k1 >> 32));
        else if (n == 2) e2 = __uint_as_float((unsigned)(k2 >> 32));
        else { e2 = 0.f; use = false; }     // exp(-d_sorted[i,n>=3]) <= exp(-27) ~ 2e-12: drop
        if (!use) continue;
        if (y[n] != yi) continue;
        float s = 0.f;
        #pragma unroll
        for (int q = 0; q < 4; ++q) {
            float dv = yo[(size_t)row * CC + lane + 32 * q] - yo[(size_t)n * CC + lane + 32 * q];
            s = fmaf(dv, dv, s);
        }
        #pragma unroll
        for (int off = 16; off; off >>= 1) s += __shfl_xor_sync(0xffffffffu, s, off);
        float dyv = sqrtf(s);
        acc += dyv * expf(-sqrtf(e2));
    }
    if (lane == 0) atomicAdd(&g_reg, acc);
}

__global__ void k_final(float* out) { out[0] = g_loss + ALPHA_ * g_reg; }

extern "C" void kernel_launch(void* const* d_in, const int* in_sizes, int n_in,
                              void* d_out, int out_size) {
    (void)in_sizes; (void)n_in; (void)out_size;
    const float* x  = (const float*)d_in[0];
    const int*   y  = (const int*)d_in[1];
    const float* yo = (const float*)d_in[2];
    const float* W  = (const float*)d_in[3];
    const float* b  = (const float*)d_in[4];
    float* out = (float*)d_out;

    k_init<<<1, 1>>>();
    k_sq<<<NN / 8, 256>>>(x);
    k_loss<<<NN / 16, 128>>>(x, y, W, b);
    k_gemm_top3<<<dim3(32, 32), 256>>>(x);
    k_merge<<<NN / 8, 256>>>();
    k_reg<<<NN / 8, 256>>>(y, yo);
    k_final<<<1, 1>>>(out);
}

// round 2
// speedup vs baseline: 1.4430x; 1.4430x over previous
#include <cuda_runtime.h>
#include <math.h>

#define NN 4096
#define DD 512
#define CC 128
#define ALPHA_ 0.0005f
#define NT 32              // number of 128-row tiles

typedef unsigned long long ull;

__device__ float g_sq[NN];
__device__ ull   g_part[NN * NT * 3];
__device__ ull   g_top3[NN * 3];
__device__ float g_loss;
__device__ float g_reg;

__device__ __forceinline__ void ins3(ull &a0, ull &a1, ull &a2, ull k) {
    if (k < a2) a2 = k;
    if (a2 < a1) { ull t = a1; a1 = a2; a2 = t; }
    if (a1 < a0) { ull t = a0; a0 = a1; a1 = t; }
}

__device__ __forceinline__ ull dup2(float a) {
    ull r; unsigned u = __float_as_uint(a);
    asm("mov.b64 %0, {%1, %1};" : "=l"(r) : "r"(u));
    return r;
}
#define FMA2(d, a, b) asm("fma.rn.f32x2 %0, %1, %2, %0;" : "+l"(d) : "l"(a), "l"(b))

__global__ void k_init() { g_loss = 0.f; g_reg = 0.f; }

__global__ void k_sq(const float* __restrict__ x) {
    int row  = (blockIdx.x * blockDim.x + threadIdx.x) >> 5;
    int lane = threadIdx.x & 31;
    const float* xr = x + (size_t)row * DD;
    float s = 0.f;
    #pragma unroll
    for (int q = 0; q < DD / 32; ++q) { float v = xr[lane + 32 * q]; s = fmaf(v, v, s); }
    #pragma unroll
    for (int off = 16; off; off >>= 1) s += __shfl_down_sync(0xffffffffu, s, off);
    if (lane == 0) g_sq[row] = s;
}

// Upper-triangular tiled x @ x^T with fused per-row AND per-col top-3.
// f32x2 packed FMAs: accumulator pairs along the column (ni) dimension.
__global__ __launch_bounds__(256) void k_gemm_top3(const float* __restrict__ x) {
    __shared__ __align__(16) float sbuf[2 * 32 * 132];
    float (*As)[132] = (float (*)[132])sbuf;
    float (*Bs)[132] = (float (*)[132])(sbuf + 32 * 132);

    int t  = threadIdx.x;
    int tx = t & 15, ty = t >> 4;

    // decode triangular block index -> (by, bx) with bx >= by
    int id = blockIdx.x, by = 0;
    while (id >= NT - by) { id -= NT - by; by++; }
    int bx = by + id;
    int rowA = by * 128, rowB = bx * 128;

    ull acc2[8][4];
    #pragma unroll
    for (int i = 0; i < 8; i++)
        #pragma unroll
        for (int j = 0; j < 4; j++) acc2[i][j] = 0ull;

    for (int k0 = 0; k0 < DD; k0 += 32) {
        #pragma unroll
        for (int it = 0; it < 4; ++it) {
            int idd = t + 256 * it;          // 0..1023 : 128 rows x 8 float4
            int r   = idd >> 3;
            int kq  = (idd & 7) << 2;
            float4 va = *(const float4*)&x[(size_t)(rowA + r) * DD + k0 + kq];
            As[kq + 0][r] = va.x; As[kq + 1][r] = va.y; As[kq + 2][r] = va.z; As[kq + 3][r] = va.w;
            float4 vb = *(const float4*)&x[(size_t)(rowB + r) * DD + k0 + kq];
            Bs[kq + 0][r] = vb.x; Bs[kq + 1][r] = vb.y; Bs[kq + 2][r] = vb.z; Bs[kq + 3][r] = vb.w;
        }
        __syncthreads();
        #pragma unroll
        for (int kk = 0; kk < 32; ++kk) {
            float4 a0 = *(const float4*)&As[kk][ty * 8];
            float4 a1 = *(const float4*)&As[kk][ty * 8 + 4];
            ull aa[8] = {dup2(a0.x), dup2(a0.y), dup2(a0.z), dup2(a0.w),
                         dup2(a1.x), dup2(a1.y), dup2(a1.z), dup2(a1.w)};
            ulonglong2 b0 = *(const ulonglong2*)&Bs[kk][tx * 8];
            ulonglong2 b1 = *(const ulonglong2*)&Bs[kk][tx * 8 + 4];
            ull bb[4] = {b0.x, b0.y, b1.x, b1.y};
            #pragma unroll
            for (int i = 0; i < 8; i++)
                #pragma unroll
                for (int j = 0; j < 4; j++)
                    FMA2(acc2[i][j], aa[i], bb[j]);
        }
        __syncthreads();
    }

    // unpack accumulators
    float acc[8][8];
    #pragma unroll
    for (int i = 0; i < 8; i++)
        #pragma unroll
        for (int j = 0; j < 4; j++) {
            acc[i][2 * j + 0] = __uint_as_float((unsigned)(acc2[i][j]));
            acc[i][2 * j + 1] = __uint_as_float((unsigned)(acc2[i][j] >> 32));
        }

    float sqa[8], sqb[8];
    #pragma unroll
    for (int i = 0; i < 8; i++) sqa[i] = g_sq[rowA + ty * 8 + i];
    #pragma unroll
    for (int j = 0; j < 8; j++) sqb[j] = g_sq[rowB + tx * 8 + j];

    // ---- row-direction top3 (rows rowA+.., candidates rowB+..), slot = bx ----
    #pragma unroll
    for (int mi = 0; mi < 8; ++mi) {
        ull t0 = ~0ull, t1 = ~0ull, t2 = ~0ull;
        #pragma unroll
        for (int ni = 0; ni < 8; ++ni) {
            float d2 = sqa[mi] + sqb[ni] - 2.f * acc[mi][ni];
            float e2 = d2 > 0.f ? d2 : 0.f;
            ull key = ((ull)__float_as_uint(e2) << 32) | (unsigned)(rowB + tx * 8 + ni);
            ins3(t0, t1, t2, key);
        }
        #pragma unroll
        for (int off = 8; off; off >>= 1) {
            ull r0 = __shfl_down_sync(0xffffffffu, t0, off, 16);
            ull r1 = __shfl_down_sync(0xffffffffu, t1, off, 16);
            ull r2 = __shfl_down_sync(0xffffffffu, t2, off, 16);
            ins3(t0, t1, t2, r0); ins3(t0, t1, t2, r1); ins3(t0, t1, t2, r2);
        }
        if (tx == 0) {
            size_t base = ((size_t)(rowA + ty * 8 + mi) * NT + bx) * 3;
            g_part[base + 0] = t0; g_part[base + 1] = t1; g_part[base + 2] = t2;
        }
    }

    // ---- col-direction top3 (rows rowB+.., candidates rowA+..), slot = by ----
    if (bx != by) {
        ull* scratch = (ull*)sbuf;       // [8 warp-groups][128 cols][3]
        int w = t >> 5, lane = t & 31;
        // last loop iteration ended with __syncthreads(): safe to overwrite sbuf
        #pragma unroll
        for (int ni = 0; ni < 8; ++ni) {
            ull t0 = ~0ull, t1 = ~0ull, t2 = ~0ull;
            #pragma unroll
            for (int mi = 0; mi < 8; ++mi) {
                float d2 = sqb[ni] + sqa[mi] - 2.f * acc[mi][ni];
                float e2 = d2 > 0.f ? d2 : 0.f;
                ull key = ((ull)__float_as_uint(e2) << 32) | (unsigned)(rowA + ty * 8 + mi);
                ins3(t0, t1, t2, key);
            }
            // combine the two ty values in this warp (lane and lane+16)
            ull r0 = __shfl_down_sync(0xffffffffu, t0, 16);
            ull r1 = __shfl_down_sync(0xffffffffu, t1, 16);
            ull r2 = __shfl_down_sync(0xffffffffu, t2, 16);
            if (lane < 16) {
                ins3(t0, t1, t2, r0); ins3(t0, t1, t2, r1); ins3(t0, t1, t2, r2);
                size_t sb = ((size_t)w * 128 + tx * 8 + ni) * 3;
                scratch[sb + 0] = t0; scratch[sb + 1] = t1; scratch[sb + 2] = t2;
            }
        }
        __syncthreads();
        if (t < 128) {
            ull t0 = ~0ull, t1 = ~0ull, t2 = ~0ull;
            #pragma unroll
            for (int g = 0; g < 8; ++g) {
                size_t sb = ((size_t)g * 128 + t) * 3;
                ins3(t0, t1, t2, scratch[sb + 0]);
                ins3(t0, t1, t2, scratch[sb + 1]);
                ins3(t0, t1, t2, scratch[sb + 2]);
            }
            size_t base = ((size_t)(rowB + t) * NT + by) * 3;
            g_part[base + 0] = t0; g_part[base + 1] = t1; g_part[base + 2] = t2;
        }
    }
}

__global__ void k_merge() {
    int row  = (blockIdx.x * blockDim.x + threadIdx.x) >> 5;
    int lane = threadIdx.x & 31;
    ull t0 = ~0ull, t1 = ~0ull, t2 = ~0ull;
    size_t base = (size_t)row * (NT * 3);
    for (int p = lane; p < NT * 3; p += 32) ins3(t0, t1, t2, g_part[base + p]);
    #pragma unroll
    for (int off = 16; off; off >>= 1) {
        ull r0 = __shfl_down_sync(0xffffffffu, t0, off);
        ull r1 = __shfl_down_sync(0xffffffffu, t1, off);
        ull r2 = __shfl_down_sync(0xffffffffu, t2, off);
        ins3(t0, t1, t2, r0); ins3(t0, t1, t2, r1); ins3(t0, t1, t2, r2);
    }
    if (lane == 0) {
        g_top3[(size_t)row * 3 + 0] = t0;
        g_top3[(size_t)row * 3 + 1] = t1;
        g_top3[(size_t)row * 3 + 2] = t2;
    }
}

__global__ __launch_bounds__(128) void k_loss(const float* __restrict__ x,
                                              const int* __restrict__ y,
                                              const float* __restrict__ W,
                                              const float* __restrict__ b) {
    __shared__ float xs[16][512];
    __shared__ float lg[16][128];
    int tid  = threadIdx.x;
    int row0 = blockIdx.x * 16;

    #pragma unroll
    for (int i = 0; i < 16; ++i) {
        int id = tid + 128 * i;
        int r  = id >> 7;
        int q  = id & 127;
        float4 v = *(const float4*)&x[(size_t)(row0 + r) * DD + q * 4];
        *(float4*)&xs[r][q * 4] = v;
    }
    __syncthreads();

    float acc[16];
    #pragma unroll
    for (int r = 0; r < 16; r++) acc[r] = 0.f;
    int c = tid;
    for (int d0 = 0; d0 < DD; d0 += 4) {
        float w0 = W[(d0 + 0) * CC + c];
        float w1 = W[(d0 + 1) * CC + c];
        float w2 = W[(d0 + 2) * CC + c];
        float w3 = W[(d0 + 3) * CC + c];
        #pragma unroll
        for (int r = 0; r < 16; r++) {
            float4 xv = *(const float4*)&xs[r][d0];
            acc[r] += xv.x * w0 + xv.y * w1 + xv.z * w2 + xv.w * w3;
        }
    }
    float bc = b[c];
    #pragma unroll
    for (int r = 0; r < 16; r++) lg[r][c] = acc[r] + bc;
    __syncthreads();

    int w = tid >> 5, lane = tid & 31;
    for (int s = 0; s < 4; ++s) {
        int r = w * 4 + s;
        float l0 = lg[r][lane], l1 = lg[r][lane + 32], l2 = lg[r][lane + 64], l3 = lg[r][lane + 96];
        float mx = fmaxf(fmaxf(l0, l1), fmaxf(l2, l3));
        #pragma unroll
        for (int off = 16; off; off >>= 1) mx = fmaxf(mx, __shfl_xor_sync(0xffffffffu, mx, off));
        float se = expf(l0 - mx) + expf(l1 - mx) + expf(l2 - mx) + expf(l3 - mx);
        #pragma unroll
        for (int off = 16; off; off >>= 1) se += __shfl_xor_sync(0xffffffffu, se, off);
        if (lane == 0) {
            int lab  = y[row0 + r];
            float ll = lg[r][lab];
            atomicAdd(&g_loss, (mx + logf(se) - ll) * (1.0f / NN));
        }
    }
}

__global__ void k_reg(const int* __restrict__ y, const float* __restrict__ yo) {
    int row  = (blockIdx.x * blockDim.x + threadIdx.x) >> 5;
    int lane = threadIdx.x & 31;
    ull k0 = g_top3[(size_t)row * 3 + 0];
    ull k1 = g_top3[(size_t)row * 3 + 1];
    ull k2 = g_top3[(size_t)row * 3 + 2];
    int yi = y[row];
    float acc = 0.f;
    #pragma unroll
    for (int tq = 0; tq < 3; ++tq) {
        ull kt = (tq == 0) ? k0 : (tq == 1) ? k1 : k2;
        int n = (int)(kt & 0xffffffffu);
        float e2;
        bool use = true;
        if      (n == 0) e2 = __uint_as_float((unsigned)(k0 >> 32));
        else if (n == 1) e2 = __uint_as_float((unsigned)(k1 >> 32));
        else if (n == 2) e2 = __uint_as_float((unsigned)(k2 >> 32));
        else { e2 = 0.f; use = false; }  // exp(-d_sorted[i, n>=3]) <= ~2e-12: drop
        if (!use) continue;
        if (y[n] != yi) continue;
        float s = 0.f;
        #pragma unroll
        for (int q = 0; q < 4; ++q) {
            float dv = yo[(size_t)row * CC + lane + 32 * q] - yo[(size_t)n * CC + lane + 32 * q];
            s = fmaf(dv, dv, s);
        }
        #pragma unroll
        for (int off = 16; off; off >>= 1) s += __shfl_xor_sync(0xffffffffu, s, off);
        float dyv = sqrtf(s);
        acc += dyv * expf(-sqrtf(e2));
    }
    if (lane == 0) atomicAdd(&g_reg, acc);
}

__global__ void k_final(float* out) { out[0] = g_loss + ALPHA_ * g_reg; }

extern "C" void kernel_launch(void* const* d_in, const int* in_sizes, int n_in,
                              void* d_out, int out_size) {
    (void)in_sizes; (void)n_in; (void)out_size;
    const float* x  = (const float*)d_in[0];
    const int*   y  = (const int*)d_in[1];
    const float* yo = (const float*)d_in[2];
    const float* W  = (const float*)d_in[3];
    const float* b  = (const float*)d_in[4];
    float* out = (float*)d_out;

    k_init<<<1, 1>>>();
    k_sq<<<NN / 8, 256>>>(x);
    k_loss<<<NN / 16, 128>>>(x, y, W, b);
    k_gemm_top3<<<NT * (NT + 1) / 2, 256>>>(x);
    k_merge<<<NN / 8, 256>>>();
    k_reg<<<NN / 8, 256>>>(y, yo);
    k_final<<<1, 1>>>(out);
}

// round 5
// speedup vs baseline: 1.5672x; 1.0861x over previous
#include <cuda_runtime.h>
#include <math.h>

#define NN 4096
#define DD 512
#define CC 128
#define ALPHA_ 0.0005f
#define NT 32              // number of 128-row tiles

typedef unsigned long long ull;

__device__ float g_sq[NN];
__device__ ull   g_part[NN * NT * 3];
__device__ ull   g_top3[NN * 3];
__device__ float g_loss;
__device__ float g_reg;

__device__ __forceinline__ void ins3(ull &a0, ull &a1, ull &a2, ull k) {
    if (k < a2) a2 = k;
    if (a2 < a1) { ull t = a1; a1 = a2; a2 = t; }
    if (a1 < a0) { ull t = a0; a0 = a1; a1 = t; }
}

__device__ __forceinline__ ull dup2(float a) {
    ull r; unsigned u = __float_as_uint(a);
    asm("mov.b64 %0, {%1, %1};" : "=l"(r) : "r"(u));
    return r;
}
#define FMA2(d, a, b) asm("fma.rn.f32x2 %0, %1, %2, %0;" : "+l"(d) : "l"(a), "l"(b))

__global__ void k_init() { g_loss = 0.f; g_reg = 0.f; }

__global__ void k_sq(const float* __restrict__ x) {
    int row  = (blockIdx.x * blockDim.x + threadIdx.x) >> 5;
    int lane = threadIdx.x & 31;
    const float* xr = x + (size_t)row * DD;
    float s = 0.f;
    #pragma unroll
    for (int q = 0; q < DD / 32; ++q) { float v = xr[lane + 32 * q]; s = fmaf(v, v, s); }
    #pragma unroll
    for (int off = 16; off; off >>= 1) s += __shfl_down_sync(0xffffffffu, s, off);
    if (lane == 0) g_sq[row] = s;
}

// Upper-triangular tiled x @ x^T with fused per-row AND per-col top-3.
// f32x2 packed FMAs, 2 CTAs/SM enforced (128-reg cap).
__global__ __launch_bounds__(256, 2) void k_gemm_top3(const float* __restrict__ x) {
    __shared__ __align__(16) float sbuf[2 * 32 * 132];
    float (*As)[132] = (float (*)[132])sbuf;
    float (*Bs)[132] = (float (*)[132])(sbuf + 32 * 132);

    int t  = threadIdx.x;
    int tx = t & 15, ty = t >> 4;

    // decode triangular block index -> (by, bx) with bx >= by
    int id = blockIdx.x, by = 0;
    while (id >= NT - by) { id -= NT - by; by++; }
    int bx = by + id;
    int rowA = by * 128, rowB = bx * 128;

    ull acc2[8][4];
    #pragma unroll
    for (int i = 0; i < 8; i++)
        #pragma unroll
        for (int j = 0; j < 4; j++) acc2[i][j] = 0ull;

    for (int k0 = 0; k0 < DD; k0 += 32) {
        #pragma unroll
        for (int it = 0; it < 4; ++it) {
            int idd = t + 256 * it;          // 0..1023 : 128 rows x 8 float4
            int r   = idd >> 3;
            int kq  = (idd & 7) << 2;
            float4 va = *(const float4*)&x[(size_t)(rowA + r) * DD + k0 + kq];
            As[kq + 0][r] = va.x; As[kq + 1][r] = va.y; As[kq + 2][r] = va.z; As[kq + 3][r] = va.w;
            float4 vb = *(const float4*)&x[(size_t)(rowB + r) * DD + k0 + kq];
            Bs[kq + 0][r] = vb.x; Bs[kq + 1][r] = vb.y; Bs[kq + 2][r] = vb.z; Bs[kq + 3][r] = vb.w;
        }
        __syncthreads();
        #pragma unroll
        for (int kk = 0; kk < 32; ++kk) {
            ulonglong2 b0 = *(const ulonglong2*)&Bs[kk][tx * 8];
            ulonglong2 b1 = *(const ulonglong2*)&Bs[kk][tx * 8 + 4];
            ull bb[4] = {b0.x, b0.y, b1.x, b1.y};
            float4 a0 = *(const float4*)&As[kk][ty * 8];
            float4 a1 = *(const float4*)&As[kk][ty * 8 + 4];
            float af[8] = {a0.x, a0.y, a0.z, a0.w, a1.x, a1.y, a1.z, a1.w};
            #pragma unroll
            for (int i = 0; i < 8; i++) {
                ull ai = dup2(af[i]);
                #pragma unroll
                for (int j = 0; j < 4; j++)
                    FMA2(acc2[i][j], ai, bb[j]);
            }
        }
        __syncthreads();
    }

    // unpack accumulators
    float acc[8][8];
    #pragma unroll
    for (int i = 0; i < 8; i++)
        #pragma unroll
        for (int j = 0; j < 4; j++) {
            acc[i][2 * j + 0] = __uint_as_float((unsigned)(acc2[i][j]));
            acc[i][2 * j + 1] = __uint_as_float((unsigned)(acc2[i][j] >> 32));
        }

    float sqa[8], sqb[8];
    #pragma unroll
    for (int i = 0; i < 8; i++) sqa[i] = g_sq[rowA + ty * 8 + i];
    #pragma unroll
    for (int j = 0; j < 8; j++) sqb[j] = g_sq[rowB + tx * 8 + j];

    // ---- row-direction top3 (rows rowA+.., candidates rowB+..), slot = bx ----
    #pragma unroll
    for (int mi = 0; mi < 8; ++mi) {
        ull t0 = ~0ull, t1 = ~0ull, t2 = ~0ull;
        #pragma unroll
        for (int ni = 0; ni < 8; ++ni) {
            float d2 = sqa[mi] + sqb[ni] - 2.f * acc[mi][ni];
            float e2 = d2 > 0.f ? d2 : 0.f;
            ull key = ((ull)__float_as_uint(e2) << 32) | (unsigned)(rowB + tx * 8 + ni);
            ins3(t0, t1, t2, key);
        }
        #pragma unroll
        for (int off = 8; off; off >>= 1) {
            ull r0 = __shfl_down_sync(0xffffffffu, t0, off, 16);
            ull r1 = __shfl_down_sync(0xffffffffu, t1, off, 16);
            ull r2 = __shfl_down_sync(0xffffffffu, t2, off, 16);
            ins3(t0, t1, t2, r0); ins3(t0, t1, t2, r1); ins3(t0, t1, t2, r2);
        }
        if (tx == 0) {
            size_t base = ((size_t)(rowA + ty * 8 + mi) * NT + bx) * 3;
            g_part[base + 0] = t0; g_part[base + 1] = t1; g_part[base + 2] = t2;
        }
    }

    // ---- col-direction top3 (rows rowB+.., candidates rowA+..), slot = by ----
    if (bx != by) {
        ull* scratch = (ull*)sbuf;       // [8 warp-groups][128 cols][3]
        int w = t >> 5, lane = t & 31;
        #pragma unroll
        for (int ni = 0; ni < 8; ++ni) {
            ull t0 = ~0ull, t1 = ~0ull, t2 = ~0ull;
            #pragma unroll
            for (int mi = 0; mi < 8; ++mi) {
                float d2 = sqb[ni] + sqa[mi] - 2.f * acc[mi][ni];
                float e2 = d2 > 0.f ? d2 : 0.f;
                ull key = ((ull)__float_as_uint(e2) << 32) | (unsigned)(rowA + ty * 8 + mi);
                ins3(t0, t1, t2, key);
            }
            ull r0 = __shfl_down_sync(0xffffffffu, t0, 16);
            ull r1 = __shfl_down_sync(0xffffffffu, t1, 16);
            ull r2 = __shfl_down_sync(0xffffffffu, t2, 16);
            if (lane < 16) {
                ins3(t0, t1, t2, r0); ins3(t0, t1, t2, r1); ins3(t0, t1, t2, r2);
                size_t sb = ((size_t)w * 128 + tx * 8 + ni) * 3;
                scratch[sb + 0] = t0; scratch[sb + 1] = t1; scratch[sb + 2] = t2;
            }
        }
        __syncthreads();
        if (t < 128) {
            ull t0 = ~0ull, t1 = ~0ull, t2 = ~0ull;
            #pragma unroll
            for (int g = 0; g < 8; ++g) {
                size_t sb = ((size_t)g * 128 + t) * 3;
                ins3(t0, t1, t2, scratch[sb + 0]);
                ins3(t0, t1, t2, scratch[sb + 1]);
                ins3(t0, t1, t2, scratch[sb + 2]);
            }
            size_t base = ((size_t)(rowB + t) * NT + by) * 3;
            g_part[base + 0] = t0; g_part[base + 1] = t1; g_part[base + 2] = t2;
        }
    }
}

__global__ void k_merge() {
    int row  = (blockIdx.x * blockDim.x + threadIdx.x) >> 5;
    int lane = threadIdx.x & 31;
    ull t0 = ~0ull, t1 = ~0ull, t2 = ~0ull;
    size_t base = (size_t)row * (NT * 3);
    for (int p = lane; p < NT * 3; p += 32) ins3(t0, t1, t2, g_part[base + p]);
    #pragma unroll
    for (int off = 16; off; off >>= 1) {
        ull r0 = __shfl_down_sync(0xffffffffu, t0, off);
        ull r1 = __shfl_down_sync(0xffffffffu, t1, off);
        ull r2 = __shfl_down_sync(0xffffffffu, t2, off);
        ins3(t0, t1, t2, r0); ins3(t0, t1, t2, r1); ins3(t0, t1, t2, r2);
    }
    if (lane == 0) {
        g_top3[(size_t)row * 3 + 0] = t0;
        g_top3[(size_t)row * 3 + 1] = t1;
        g_top3[(size_t)row * 3 + 2] = t2;
    }
}

__global__ __launch_bounds__(128) void k_loss(const float* __restrict__ x,
                                              const int* __restrict__ y,
                                              const float* __restrict__ W,
                                              const float* __restrict__ b) {
    __shared__ float xs[16][512];
    __shared__ float lg[16][128];
    int tid  = threadIdx.x;
    int row0 = blockIdx.x * 16;

    #pragma unroll
    for (int i = 0; i < 16; ++i) {
        int id = tid + 128 * i;
        int r  = id >> 7;
        int q  = id & 127;
        float4 v = *(const float4*)&x[(size_t)(row0 + r) * DD + q * 4];
        *(float4*)&xs[r][q * 4] = v;
    }
    __syncthreads();

    float acc[16];
    #pragma unroll
    for (int r = 0; r < 16; r++) acc[r] = 0.f;
    int c = tid;
    for (int d0 = 0; d0 < DD; d0 += 4) {
        float w0 = W[(d0 + 0) * CC + c];
        float w1 = W[(d0 + 1) * CC + c];
        float w2 = W[(d0 + 2) * CC + c];
        float w3 = W[(d0 + 3) * CC + c];
        #pragma unroll
        for (int r = 0; r < 16; r++) {
            float4 xv = *(const float4*)&xs[r][d0];
            acc[r] += xv.x * w0 + xv.y * w1 + xv.z * w2 + xv.w * w3;
        }
    }
    float bc = b[c];
    #pragma unroll
    for (int r = 0; r < 16; r++) lg[r][c] = acc[r] + bc;
    __syncthreads();

    int w = tid >> 5, lane = tid & 31;
    for (int s = 0; s < 4; ++s) {
        int r = w * 4 + s;
        float l0 = lg[r][lane], l1 = lg[r][lane + 32], l2 = lg[r][lane + 64], l3 = lg[r][lane + 96];
        float mx = fmaxf(fmaxf(l0, l1), fmaxf(l2, l3));
        #pragma unroll
        for (int off = 16; off; off >>= 1) mx = fmaxf(mx, __shfl_xor_sync(0xffffffffu, mx, off));
        float se = expf(l0 - mx) + expf(l1 - mx) + expf(l2 - mx) + expf(l3 - mx);
        #pragma unroll
        for (int off = 16; off; off >>= 1) se += __shfl_xor_sync(0xffffffffu, se, off);
        if (lane == 0) {
            int lab  = y[row0 + r];
            float ll = lg[r][lab];
            atomicAdd(&g_loss, (mx + logf(se) - ll) * (1.0f / NN));
        }
    }
}

__global__ void k_reg(const int* __restrict__ y, const float* __restrict__ yo) {
    int row  = (blockIdx.x * blockDim.x + threadIdx.x) >> 5;
    int lane = threadIdx.x & 31;
    ull k0 = g_top3[(size_t)row * 3 + 0];
    ull k1 = g_top3[(size_t)row * 3 + 1];
    ull k2 = g_top3[(size_t)row * 3 + 2];
    int yi = y[row];
    float acc = 0.f;
    #pragma unroll
    for (int tq = 0; tq < 3; ++tq) {
        ull kt = (tq == 0) ? k0 : (tq == 1) ? k1 : k2;
        int n = (int)(kt & 0xffffffffu);
        float e2;
        bool use = true;
        if      (n == 0) e2 = __uint_as_float((unsigned)(k0 >> 32));
        else if (n == 1) e2 = __uint_as_float((unsigned)(k1 >> 32));
        else if (n == 2) e2 = __uint_as_float((unsigned)(k2 >> 32));
        else { e2 = 0.f; use = false; }  // exp(-d_sorted[i, n>=3]) <= ~2e-12: drop
        if (!use) continue;
        if (y[n] != yi) continue;
        float s = 0.f;
        #pragma unroll
        for (int q = 0; q < 4; ++q) {
            float dv = yo[(size_t)row * CC + lane + 32 * q] - yo[(size_t)n * CC + lane + 32 * q];
            s = fmaf(dv, dv, s);
        }
        #pragma unroll
        for (int off = 16; off; off >>= 1) s += __shfl_xor_sync(0xffffffffu, s, off);
        float dyv = sqrtf(s);
        acc += dyv * expf(-sqrtf(e2));
    }
    if (lane == 0) atomicAdd(&g_reg, acc);
}

__global__ void k_final(float* out) { out[0] = g_loss + ALPHA_ * g_reg; }

extern "C" void kernel_launch(void* const* d_in, const int* in_sizes, int n_in,
                              void* d_out, int out_size) {
    (void)in_sizes; (void)n_in; (void)out_size;
    const float* x  = (const float*)d_in[0];
    const int*   y  = (const int*)d_in[1];
    const float* yo = (const float*)d_in[2];
    const float* W  = (const float*)d_in[3];
    const float* b  = (const float*)d_in[4];
    float* out = (float*)d_out;

    k_init<<<1, 1>>>();
    k_sq<<<NN / 8, 256>>>(x);
    k_loss<<<NN / 16, 128>>>(x, y, W, b);
    k_gemm_top3<<<NT * (NT + 1) / 2, 256>>>(x);
    k_merge<<<NN / 8, 256>>>();
    k_reg<<<NN / 8, 256>>>(y, yo);
    k_final<<<1, 1>>>(out);
}

// round 7
// speedup vs baseline: 2.5089x; 1.6008x over previous
#include <cuda_runtime.h>
#include <cuda_bf16.h>
#include <math.h>

#define NN 4096
#define DD 512
#define CC 128
#define ALPHA_ 0.0005f
#define NT 32

typedef unsigned long long ull;

__device__ float g_sq[NN];
__device__ ull   g_part[NN * NT * 3];
__device__ ull   g_top3[NN * 3];
__device__ float g_loss;
__device__ float g_reg;
__device__ __nv_bfloat16 g_xhi[NN * DD];
__device__ __nv_bfloat16 g_xlo[NN * DD];

__device__ __forceinline__ void ins3(ull &a0, ull &a1, ull &a2, ull k) {
    if (k < a2) a2 = k;
    if (a2 < a1) { ull t = a1; a1 = a2; a2 = t; }
    if (a1 < a0) { ull t = a0; a0 = a1; a1 = t; }
}

__device__ __forceinline__ unsigned smem_u32(const void* p) {
    unsigned a;
    asm("{ .reg .u64 t; cvta.to.shared.u64 t, %1; cvt.u32.u64 %0, t; }" : "=r"(a) : "l"(p));
    return a;
}

#define LDSMX4(r0, r1, r2, r3, addr) \
    asm volatile("ldmatrix.sync.aligned.m8n8.x4.shared.b16 {%0,%1,%2,%3}, [%4];" \
        : "=r"(r0), "=r"(r1), "=r"(r2), "=r"(r3) : "r"(addr))

#define MMA16816(d, a, b) \
    asm volatile("mma.sync.aligned.m16n8k16.row.col.f32.bf16.bf16.f32 " \
        "{%0,%1,%2,%3}, {%4,%5,%6,%7}, {%8,%9}, {%0,%1,%2,%3};" \
        : "+f"((d)[0]), "+f"((d)[1]), "+f"((d)[2]), "+f"((d)[3]) \
        : "r"((a)[0]), "r"((a)[1]), "r"((a)[2]), "r"((a)[3]), "r"((b)[0]), "r"((b)[1]))

__global__ void k_init() { g_loss = 0.f; g_reg = 0.f; }

__global__ void k_cvt(const float* __restrict__ x) {
    int i = (blockIdx.x * blockDim.x + threadIdx.x) * 4;
    float4 v = *(const float4*)(x + i);
    __nv_bfloat16 h0 = __float2bfloat16(v.x), h1 = __float2bfloat16(v.y);
    __nv_bfloat16 h2 = __float2bfloat16(v.z), h3 = __float2bfloat16(v.w);
    __nv_bfloat16 l0 = __float2bfloat16(v.x - __bfloat162float(h0));
    __nv_bfloat16 l1 = __float2bfloat16(v.y - __bfloat162float(h1));
    __nv_bfloat16 l2 = __float2bfloat16(v.z - __bfloat162float(h2));
    __nv_bfloat16 l3 = __float2bfloat16(v.w - __bfloat162float(h3));
    __nv_bfloat162 hA; hA.x = h0; hA.y = h1;
    __nv_bfloat162 hB; hB.x = h2; hB.y = h3;
    __nv_bfloat162 lA; lA.x = l0; lA.y = l1;
    __nv_bfloat162 lB; lB.x = l2; lB.y = l3;
    *(__nv_bfloat162*)(g_xhi + i)     = hA;
    *(__nv_bfloat162*)(g_xhi + i + 2) = hB;
    *(__nv_bfloat162*)(g_xlo + i)     = lA;
    *(__nv_bfloat162*)(g_xlo + i + 2) = lB;
}

__global__ void k_sq(const float* __restrict__ x) {
    int row  = (blockIdx.x * blockDim.x + threadIdx.x) >> 5;
    int lane = threadIdx.x & 31;
    const float* xr = x + (size_t)row * DD;
    float s = 0.f;
    #pragma unroll
    for (int q = 0; q < DD / 32; ++q) { float v = xr[lane + 32 * q]; s = fmaf(v, v, s); }
    #pragma unroll
    for (int off = 16; off; off >>= 1) s += __shfl_down_sync(0xffffffffu, s, off);
    if (lane == 0) g_sq[row] = s;
}

// ---------------- mma.sync bf16 distance GEMM + fused dual top-3 ----------------
__global__ __launch_bounds__(256, 2) void k_mma_top3() {
    __shared__ __align__(16) __nv_bfloat16 sA[2][128][40];   // [hi/lo][row][k], pitch 40
    __shared__ __align__(16) __nv_bfloat16 sB[2][128][40];
    __shared__ float s_sq[2][128];

    int t = threadIdx.x, lane = t & 31, wid = t >> 5;
    int wm = wid >> 1, wn = wid & 1;
    int mbase = wm * 32, nbase = wn * 64;

    // triangular block decode
    int id = blockIdx.x, by = 0;
    while (id >= NT - by) { id -= NT - by; by++; }
    int bx = by + id;
    int rowA = by * 128, rowB = bx * 128;

    if (t < 128) { s_sq[0][t] = g_sq[rowA + t]; s_sq[1][t] = g_sq[rowB + t]; }

    float acc[2][8][4];
    #pragma unroll
    for (int i = 0; i < 2; i++)
        #pragma unroll
        for (int j = 0; j < 8; j++)
            #pragma unroll
            for (int k = 0; k < 4; k++) acc[i][j][k] = 0.f;

    unsigned baseAh = smem_u32(&sA[0][0][0]);
    unsigned baseAl = smem_u32(&sA[1][0][0]);
    unsigned baseBh = smem_u32(&sB[0][0][0]);
    unsigned baseBl = smem_u32(&sB[1][0][0]);
    // ldmatrix address offsets (bytes)
    unsigned aRowOff = ((mbase + (lane & 15)) * 40 + (lane >> 4) * 8) * 2;
    unsigned bRowOff = ((nbase + (lane & 7) + ((lane >> 4) << 3)) * 40 + ((lane >> 3) & 1) * 8) * 2;

    for (int s = 0; s < 16; ++s) {
        int k0 = s * 32;
        #pragma unroll
        for (int c = 0; c < 2; ++c) {
            int i = t + 256 * c;           // 0..511
            int r = i >> 2, q = i & 3;     // row, 16B chunk
            size_t gA = (size_t)(rowA + r) * DD + k0 + q * 8;
            size_t gB = (size_t)(rowB + r) * DD + k0 + q * 8;
            *(float4*)&sA[0][r][q * 8] = *(const float4*)(g_xhi + gA);
            *(float4*)&sA[1][r][q * 8] = *(const float4*)(g_xlo + gA);
            *(float4*)&sB[0][r][q * 8] = *(const float4*)(g_xhi + gB);
            *(float4*)&sB[1][r][q * 8] = *(const float4*)(g_xlo + gB);
        }
        __syncthreads();

        #pragma unroll
        for (int kh = 0; kh < 2; ++kh) {
            unsigned ko = kh * 32;         // 16 elements * 2 bytes
            unsigned aH[2][4], aL[2][4], bb[8][2];
            LDSMX4(aH[0][0], aH[0][1], aH[0][2], aH[0][3], baseAh + aRowOff + ko);
            LDSMX4(aH[1][0], aH[1][1], aH[1][2], aH[1][3], baseAh + aRowOff + 16 * 80 + ko);
            LDSMX4(aL[0][0], aL[0][1], aL[0][2], aL[0][3], baseAl + aRowOff + ko);
            LDSMX4(aL[1][0], aL[1][1], aL[1][2], aL[1][3], baseAl + aRowOff + 16 * 80 + ko);
            // B hi: products hi*hi and lo*hi
            #pragma unroll
            for (int g = 0; g < 4; ++g)
                LDSMX4(bb[2*g][0], bb[2*g][1], bb[2*g+1][0], bb[2*g+1][1],
                       baseBh + bRowOff + g * 16 * 80 + ko);
            #pragma unroll
            for (int mt = 0; mt < 2; ++mt)
                #pragma unroll
                for (int nt = 0; nt < 8; ++nt) {
                    MMA16816(acc[mt][nt], aH[mt], bb[nt]);
                    MMA16816(acc[mt][nt], aL[mt], bb[nt]);
                }
            // B lo: product hi*lo
            #pragma unroll
            for (int g = 0; g < 4; ++g)
                LDSMX4(bb[2*g][0], bb[2*g][1], bb[2*g+1][0], bb[2*g+1][1],
                       baseBl + bRowOff + g * 16 * 80 + ko);
            #pragma unroll
            for (int mt = 0; mt < 2; ++mt)
                #pragma unroll
                for (int nt = 0; nt < 8; ++nt)
                    MMA16816(acc[mt][nt], aH[mt], bb[nt]);
        }
        __syncthreads();
    }

    // ---- convert acc -> clamped d^2 (force exact-zero diagonal) ----
    const float* sqa = s_sq[0];
    const float* sqb = s_sq[1];
    #pragma unroll
    for (int mt = 0; mt < 2; ++mt)
        #pragma unroll
        for (int nt = 0; nt < 8; ++nt)
            #pragma unroll
            for (int c4 = 0; c4 < 4; ++c4) {
                int h = c4 >> 1, c = c4 & 1;
                int ml = mbase + mt * 16 + (lane >> 2) + h * 8;
                int nl = nbase + nt * 8 + 2 * (lane & 3) + c;
                float d2 = sqa[ml] + sqb[nl] - 2.f * acc[mt][nt][c4];
                float e2 = d2 > 0.f ? d2 : 0.f;
                if (rowA + ml == rowB + nl) e2 = 0.f;
                acc[mt][nt][c4] = e2;
            }

    // partials overlay the tile buffers (all warps passed the last __syncthreads)
    ull* p_r = (ull*)&sA[0][0][0];   // [128][2][3]
    ull* p_c = (ull*)&sB[0][0][0];   // [128][4][3]

    // ---- row-direction top3 ----
    #pragma unroll
    for (int mt = 0; mt < 2; ++mt)
        #pragma unroll
        for (int h = 0; h < 2; ++h) {
            int ml = mbase + mt * 16 + (lane >> 2) + h * 8;
            ull t0 = ~0ull, t1 = ~0ull, t2 = ~0ull;
            #pragma unroll
            for (int nt = 0; nt < 8; ++nt)
                #pragma unroll
                for (int c = 0; c < 1 + 1; ++c) {
                    int nl = nbase + nt * 8 + 2 * (lane & 3) + c;
                    ull key = ((ull)__float_as_uint(acc[mt][nt][2 * h + c]) << 32) | (unsigned)(rowB + nl);
                    ins3(t0, t1, t2, key);
                }
            #pragma unroll
            for (int off = 1; off <= 2; off <<= 1) {
                ull r0 = __shfl_xor_sync(0xffffffffu, t0, off);
                ull r1 = __shfl_xor_sync(0xffffffffu, t1, off);
                ull r2 = __shfl_xor_sync(0xffffffffu, t2, off);
                ins3(t0, t1, t2, r0); ins3(t0, t1, t2, r1); ins3(t0, t1, t2, r2);
            }
            if ((lane & 3) == 0) {
                size_t b = ((size_t)ml * 2 + wn) * 3;
                p_r[b + 0] = t0; p_r[b + 1] = t1; p_r[b + 2] = t2;
            }
        }

    // ---- col-direction top3 ----
    if (bx != by) {
        #pragma unroll
        for (int nt = 0; nt < 8; ++nt)
            #pragma unroll
            for (int c = 0; c < 2; ++c) {
                int nl = nbase + nt * 8 + 2 * (lane & 3) + c;
                ull t0 = ~0ull, t1 = ~0ull, t2 = ~0ull;
                #pragma unroll
                for (int mt = 0; mt < 2; ++mt)
                    #pragma unroll
                    for (int h = 0; h < 2; ++h) {
                        int ml = mbase + mt * 16 + (lane >> 2) + h * 8;
                        ull key = ((ull)__float_as_uint(acc[mt][nt][2 * h + c]) << 32) | (unsigned)(rowA + ml);
                        ins3(t0, t1, t2, key);
                    }
                #pragma unroll
                for (int off = 4; off <= 16; off <<= 1) {
                    ull r0 = __shfl_xor_sync(0xffffffffu, t0, off);
                    ull r1 = __shfl_xor_sync(0xffffffffu, t1, off);
                    ull r2 = __shfl_xor_sync(0xffffffffu, t2, off);
                    ins3(t0, t1, t2, r0); ins3(t0, t1, t2, r1); ins3(t0, t1, t2, r2);
                }
                if (lane < 4) {
                    size_t b = ((size_t)nl * 4 + wm) * 3;
                    p_c[b + 0] = t0; p_c[b + 1] = t1; p_c[b + 2] = t2;
                }
            }
    }

    __syncthreads();
    if (t < 128) {
        ull t0 = ~0ull, t1 = ~0ull, t2 = ~0ull;
        #pragma unroll
        for (int g = 0; g < 6; ++g) ins3(t0, t1, t2, p_r[(size_t)t * 6 + g]);
        size_t base = ((size_t)(rowA + t) * NT + bx) * 3;
        g_part[base + 0] = t0; g_part[base + 1] = t1; g_part[base + 2] = t2;
    } else if (bx != by) {
        int n = t - 128;
        ull t0 = ~0ull, t1 = ~0ull, t2 = ~0ull;
        #pragma unroll
        for (int g = 0; g < 12; ++g) ins3(t0, t1, t2, p_c[(size_t)n * 12 + g]);
        size_t base = ((size_t)(rowB + n) * NT + by) * 3;
        g_part[base + 0] = t0; g_part[base + 1] = t1; g_part[base + 2] = t2;
    }
}

// ---------------- merge / loss / reg / final (unchanged, proven) ----------------
__global__ void k_merge() {
    int row  = (blockIdx.x * blockDim.x + threadIdx.x) >> 5;
    int lane = threadIdx.x & 31;
    ull t0 = ~0ull, t1 = ~0ull, t2 = ~0ull;
    size_t base = (size_t)row * (NT * 3);
    for (int p = lane; p < NT * 3; p += 32) ins3(t0, t1, t2, g_part[base + p]);
    #pragma unroll
    for (int off = 16; off; off >>= 1) {
        ull r0 = __shfl_down_sync(0xffffffffu, t0, off);
        ull r1 = __shfl_down_sync(0xffffffffu, t1, off);
        ull r2 = __shfl_down_sync(0xffffffffu, t2, off);
        ins3(t0, t1, t2, r0); ins3(t0, t1, t2, r1); ins3(t0, t1, t2, r2);
    }
    if (lane == 0) {
        g_top3[(size_t)row * 3 + 0] = t0;
        g_top3[(size_t)row * 3 + 1] = t1;
        g_top3[(size_t)row * 3 + 2] = t2;
    }
}

__global__ __launch_bounds__(128) void k_loss(const float* __restrict__ x,
                                              const int* __restrict__ y,
                                              const float* __restrict__ W,
                                              const float* __restrict__ b) {
    __shared__ float xs[16][512];
    __shared__ float lg[16][128];
    int tid  = threadIdx.x;
    int row0 = blockIdx.x * 16;

    #pragma unroll
    for (int i = 0; i < 16; ++i) {
        int id = tid + 128 * i;
        int r  = id >> 7;
        int q  = id & 127;
        float4 v = *(const float4*)&x[(size_t)(row0 + r) * DD + q * 4];
        *(float4*)&xs[r][q * 4] = v;
    }
    __syncthreads();

    float acc[16];
    #pragma unroll
    for (int r = 0; r < 16; r++) acc[r] = 0.f;
    int c = tid;
    for (int d0 = 0; d0 < DD; d0 += 4) {
        float w0 = W[(d0 + 0) * CC + c];
        float w1 = W[(d0 + 1) * CC + c];
        float w2 = W[(d0 + 2) * CC + c];
        float w3 = W[(d0 + 3) * CC + c];
        #pragma unroll
        for (int r = 0; r < 16; r++) {
            float4 xv = *(const float4*)&xs[r][d0];
            acc[r] += xv.x * w0 + xv.y * w1 + xv.z * w2 + xv.w * w3;
        }
    }
    float bc = b[c];
    #pragma unroll
    for (int r = 0; r < 16; r++) lg[r][c] = acc[r] + bc;
    __syncthreads();

    int w = tid >> 5, lane = tid & 31;
    for (int s = 0; s < 4; ++s) {
        int r = w * 4 + s;
        float l0 = lg[r][lane], l1 = lg[r][lane + 32], l2 = lg[r][lane + 64], l3 = lg[r][lane + 96];
        float mx = fmaxf(fmaxf(l0, l1), fmaxf(l2, l3));
        #pragma unroll
        for (int off = 16; off; off >>= 1) mx = fmaxf(mx, __shfl_xor_sync(0xffffffffu, mx, off));
        float se = expf(l0 - mx) + expf(l1 - mx) + expf(l2 - mx) + expf(l3 - mx);
        #pragma unroll
        for (int off = 16; off; off >>= 1) se += __shfl_xor_sync(0xffffffffu, se, off);
        if (lane == 0) {
            int lab  = y[row0 + r];
            float ll = lg[r][lab];
            atomicAdd(&g_loss, (mx + logf(se) - ll) * (1.0f / NN));
        }
    }
}

__global__ void k_reg(const int* __restrict__ y, const float* __restrict__ yo) {
    int row  = (blockIdx.x * blockDim.x + threadIdx.x) >> 5;
    int lane = threadIdx.x & 31;
    ull k0 = g_top3[(size_t)row * 3 + 0];
    ull k1 = g_top3[(size_t)row * 3 + 1];
    ull k2 = g_top3[(size_t)row * 3 + 2];
    int yi = y[row];
    float acc = 0.f;
    #pragma unroll
    for (int tq = 0; tq < 3; ++tq) {
        ull kt = (tq == 0) ? k0 : (tq == 1) ? k1 : k2;
        int n = (int)(kt & 0xffffffffu);
        float e2;
        bool use = true;
        if      (n == 0) e2 = __uint_as_float((unsigned)(k0 >> 32));
        else if (n == 1) e2 = __uint_as_float((unsigned)(k1 >> 32));
        else if (n == 2) e2 = __uint_as_float((unsigned)(k2 >> 32));
        else { e2 = 0.f; use = false; }  // exp(-d_sorted[i, n>=3]) <= ~2e-12: drop
        if (!use) continue;
        if (y[n] != yi) continue;
        float s = 0.f;
        #pragma unroll
        for (int q = 0; q < 4; ++q) {
            float dv = yo[(size_t)row * CC + lane + 32 * q] - yo[(size_t)n * CC + lane + 32 * q];
            s = fmaf(dv, dv, s);
        }
        #pragma unroll
        for (int off = 16; off; off >>= 1) s += __shfl_xor_sync(0xffffffffu, s, off);
        float dyv = sqrtf(s);
        acc += dyv * expf(-sqrtf(e2));
    }
    if (lane == 0) atomicAdd(&g_reg, acc);
}

__global__ void k_final(float* out) { out[0] = g_loss + ALPHA_ * g_reg; }

extern "C" void kernel_launch(void* const* d_in, const int* in_sizes, int n_in,
                              void* d_out, int out_size) {
    (void)in_sizes; (void)n_in; (void)out_size;
    const float* x  = (const float*)d_in[0];
    const int*   y  = (const int*)d_in[1];
    const float* yo = (const float*)d_in[2];
    const float* W  = (const float*)d_in[3];
    const float* b  = (const float*)d_in[4];
    float* out = (float*)d_out;

    k_init<<<1, 1>>>();
    k_cvt<<<NN * DD / 1024, 256>>>(x);
    k_sq<<<NN / 8, 256>>>(x);
    k_loss<<<NN / 16, 128>>>(x, y, W, b);
    k_mma_top3<<<NT * (NT + 1) / 2, 256>>>();
    k_merge<<<NN / 8, 256>>>();
    k_reg<<<NN / 8, 256>>>(y, yo);
    k_final<<<1, 1>>>(out);
}

// round 9
// speedup vs baseline: 2.8028x; 1.1171x over previous
#include <cuda_runtime.h>
#include <cuda_bf16.h>
#include <math.h>

#define NN 4096
#define DD 512
#define CC 128
#define ALPHA_ 0.0005f
#define NT 32

typedef unsigned long long ull;

__device__ float g_sq[NN];
__device__ ull   g_part[NN * NT * 3];
__device__ ull   g_top3[NN * 3];
__device__ float g_loss;
__device__ float g_reg;
__device__ __nv_bfloat16 g_xhi[NN * DD];
__device__ __nv_bfloat16 g_xlo[NN * DD];

__device__ __forceinline__ void ins3(ull &a0, ull &a1, ull &a2, ull k) {
    if (k < a2) a2 = k;
    if (a2 < a1) { ull t = a1; a1 = a2; a2 = t; }
    if (a1 < a0) { ull t = a0; a0 = a1; a1 = t; }
}

__device__ __forceinline__ unsigned smem_u32(const void* p) {
    unsigned a;
    asm("{ .reg .u64 t; cvta.to.shared.u64 t, %1; cvt.u32.u64 %0, t; }" : "=r"(a) : "l"(p));
    return a;
}

#define LDSMX4(r0, r1, r2, r3, addr) \
    asm volatile("ldmatrix.sync.aligned.m8n8.x4.shared.b16 {%0,%1,%2,%3}, [%4];" \
        : "=r"(r0), "=r"(r1), "=r"(r2), "=r"(r3) : "r"(addr))

#define MMA16816(d, a, b) \
    asm volatile("mma.sync.aligned.m16n8k16.row.col.f32.bf16.bf16.f32 " \
        "{%0,%1,%2,%3}, {%4,%5,%6,%7}, {%8,%9}, {%0,%1,%2,%3};" \
        : "+f"((d)[0]), "+f"((d)[1]), "+f"((d)[2]), "+f"((d)[3]) \
        : "r"((a)[0]), "r"((a)[1]), "r"((a)[2]), "r"((a)[3]), "r"((b)[0]), "r"((b)[1]))

__global__ void k_init() { g_loss = 0.f; g_reg = 0.f; }

// fused: bf16 hi/lo split + per-row squared norm (one pass over x)
__global__ void k_cvt_sq(const float* __restrict__ x) {
    int row  = (blockIdx.x * blockDim.x + threadIdx.x) >> 5;
    int lane = threadIdx.x & 31;
    float s = 0.f;
    #pragma unroll
    for (int q = 0; q < 4; ++q) {
        size_t i = (size_t)row * DD + lane * 4 + q * 128;
        float4 v = *(const float4*)(x + i);
        s = fmaf(v.x, v.x, s); s = fmaf(v.y, v.y, s);
        s = fmaf(v.z, v.z, s); s = fmaf(v.w, v.w, s);
        __nv_bfloat16 h0 = __float2bfloat16(v.x), h1 = __float2bfloat16(v.y);
        __nv_bfloat16 h2 = __float2bfloat16(v.z), h3 = __float2bfloat16(v.w);
        __nv_bfloat16 l0 = __float2bfloat16(v.x - __bfloat162float(h0));
        __nv_bfloat16 l1 = __float2bfloat16(v.y - __bfloat162float(h1));
        __nv_bfloat16 l2 = __float2bfloat16(v.z - __bfloat162float(h2));
        __nv_bfloat16 l3 = __float2bfloat16(v.w - __bfloat162float(h3));
        __nv_bfloat162 hA; hA.x = h0; hA.y = h1;
        __nv_bfloat162 hB; hB.x = h2; hB.y = h3;
        __nv_bfloat162 lA; lA.x = l0; lA.y = l1;
        __nv_bfloat162 lB; lB.x = l2; lB.y = l3;
        *(__nv_bfloat162*)(g_xhi + i)     = hA;
        *(__nv_bfloat162*)(g_xhi + i + 2) = hB;
        *(__nv_bfloat162*)(g_xlo + i)     = lA;
        *(__nv_bfloat162*)(g_xlo + i + 2) = lB;
    }
    #pragma unroll
    for (int off = 16; off; off >>= 1) s += __shfl_down_sync(0xffffffffu, s, off);
    if (lane == 0) g_sq[row] = s;
}

// ---------------- mma.sync bf16 distance GEMM + fused dual top-3 ----------------
__global__ __launch_bounds__(256, 2) void k_mma_top3() {
    __shared__ __align__(16) __nv_bfloat16 sA[2][128][40];   // [hi/lo][row][k], pitch 40
    __shared__ __align__(16) __nv_bfloat16 sB[2][128][40];
    __shared__ float s_sq[2][128];

    int t = threadIdx.x, lane = t & 31, wid = t >> 5;
    int wm = wid >> 1, wn = wid & 1;
    int mbase = wm * 32, nbase = wn * 64;

    int id = blockIdx.x, by = 0;
    while (id >= NT - by) { id -= NT - by; by++; }
    int bx = by + id;
    int rowA = by * 128, rowB = bx * 128;

    if (t < 128) { s_sq[0][t] = g_sq[rowA + t]; s_sq[1][t] = g_sq[rowB + t]; }

    float acc[2][8][4];
    #pragma unroll
    for (int i = 0; i < 2; i++)
        #pragma unroll
        for (int j = 0; j < 8; j++)
            #pragma unroll
            for (int k = 0; k < 4; k++) acc[i][j][k] = 0.f;

    unsigned baseAh = smem_u32(&sA[0][0][0]);
    unsigned baseAl = smem_u32(&sA[1][0][0]);
    unsigned baseBh = smem_u32(&sB[0][0][0]);
    unsigned baseBl = smem_u32(&sB[1][0][0]);
    unsigned aRowOff = ((mbase + (lane & 15)) * 40 + (lane >> 4) * 8) * 2;
    unsigned bRowOff = ((nbase + (lane & 7) + ((lane >> 4) << 3)) * 40 + ((lane >> 3) & 1) * 8) * 2;

    for (int s = 0; s < 16; ++s) {
        int k0 = s * 32;
        #pragma unroll
        for (int c = 0; c < 2; ++c) {
            int i = t + 256 * c;
            int r = i >> 2, q = i & 3;
            size_t gA = (size_t)(rowA + r) * DD + k0 + q * 8;
            size_t gB = (size_t)(rowB + r) * DD + k0 + q * 8;
            *(float4*)&sA[0][r][q * 8] = *(const float4*)(g_xhi + gA);
            *(float4*)&sA[1][r][q * 8] = *(const float4*)(g_xlo + gA);
            *(float4*)&sB[0][r][q * 8] = *(const float4*)(g_xhi + gB);
            *(float4*)&sB[1][r][q * 8] = *(const float4*)(g_xlo + gB);
        }
        __syncthreads();

        #pragma unroll
        for (int kh = 0; kh < 2; ++kh) {
            unsigned ko = kh * 32;
            unsigned aH[2][4], aL[2][4], bb[8][2];
            LDSMX4(aH[0][0], aH[0][1], aH[0][2], aH[0][3], baseAh + aRowOff + ko);
            LDSMX4(aH[1][0], aH[1][1], aH[1][2], aH[1][3], baseAh + aRowOff + 16 * 80 + ko);
            LDSMX4(aL[0][0], aL[0][1], aL[0][2], aL[0][3], baseAl + aRowOff + ko);
            LDSMX4(aL[1][0], aL[1][1], aL[1][2], aL[1][3], baseAl + aRowOff + 16 * 80 + ko);
            #pragma unroll
            for (int g = 0; g < 4; ++g)
                LDSMX4(bb[2*g][0], bb[2*g][1], bb[2*g+1][0], bb[2*g+1][1],
                       baseBh + bRowOff + g * 16 * 80 + ko);
            #pragma unroll
            for (int mt = 0; mt < 2; ++mt)
                #pragma unroll
                for (int nt = 0; nt < 8; ++nt) {
                    MMA16816(acc[mt][nt], aH[mt], bb[nt]);
                    MMA16816(acc[mt][nt], aL[mt], bb[nt]);
                }
            #pragma unroll
            for (int g = 0; g < 4; ++g)
                LDSMX4(bb[2*g][0], bb[2*g][1], bb[2*g+1][0], bb[2*g+1][1],
                       baseBl + bRowOff + g * 16 * 80 + ko);
            #pragma unroll
            for (int mt = 0; mt < 2; ++mt)
                #pragma unroll
                for (int nt = 0; nt < 8; ++nt)
                    MMA16816(acc[mt][nt], aH[mt], bb[nt]);
        }
        __syncthreads();
    }

    const float* sqa = s_sq[0];
    const float* sqb = s_sq[1];
    #pragma unroll
    for (int mt = 0; mt < 2; ++mt)
        #pragma unroll
        for (int nt = 0; nt < 8; ++nt)
            #pragma unroll
            for (int c4 = 0; c4 < 4; ++c4) {
                int h = c4 >> 1, c = c4 & 1;
                int ml = mbase + mt * 16 + (lane >> 2) + h * 8;
                int nl = nbase + nt * 8 + 2 * (lane & 3) + c;
                float d2 = sqa[ml] + sqb[nl] - 2.f * acc[mt][nt][c4];
                float e2 = d2 > 0.f ? d2 : 0.f;
                if (rowA + ml == rowB + nl) e2 = 0.f;
                acc[mt][nt][c4] = e2;
            }

    ull* p_r = (ull*)&sA[0][0][0];   // [128][2][3]
    ull* p_c = (ull*)&sB[0][0][0];   // [128][4][3]

    #pragma unroll
    for (int mt = 0; mt < 2; ++mt)
        #pragma unroll
        for (int h = 0; h < 2; ++h) {
            int ml = mbase + mt * 16 + (lane >> 2) + h * 8;
            ull t0 = ~0ull, t1 = ~0ull, t2 = ~0ull;
            #pragma unroll
            for (int nt = 0; nt < 8; ++nt)
                #pragma unroll
                for (int c = 0; c < 2; ++c) {
                    int nl = nbase + nt * 8 + 2 * (lane & 3) + c;
                    ull key = ((ull)__float_as_uint(acc[mt][nt][2 * h + c]) << 32) | (unsigned)(rowB + nl);
                    ins3(t0, t1, t2, key);
                }
            #pragma unroll
            for (int off = 1; off <= 2; off <<= 1) {
                ull r0 = __shfl_xor_sync(0xffffffffu, t0, off);
                ull r1 = __shfl_xor_sync(0xffffffffu, t1, off);
                ull r2 = __shfl_xor_sync(0xffffffffu, t2, off);
                ins3(t0, t1, t2, r0); ins3(t0, t1, t2, r1); ins3(t0, t1, t2, r2);
            }
            if ((lane & 3) == 0) {
                size_t b = ((size_t)ml * 2 + wn) * 3;
                p_r[b + 0] = t0; p_r[b + 1] = t1; p_r[b + 2] = t2;
            }
        }

    if (bx != by) {
        #pragma unroll
        for (int nt = 0; nt < 8; ++nt)
            #pragma unroll
            for (int c = 0; c < 2; ++c) {
                int nl = nbase + nt * 8 + 2 * (lane & 3) + c;
                ull t0 = ~0ull, t1 = ~0ull, t2 = ~0ull;
                #pragma unroll
                for (int mt = 0; mt < 2; ++mt)
                    #pragma unroll
                    for (int h = 0; h < 2; ++h) {
                        int ml = mbase + mt * 16 + (lane >> 2) + h * 8;
                        ull key = ((ull)__float_as_uint(acc[mt][nt][2 * h + c]) << 32) | (unsigned)(rowA + ml);
                        ins3(t0, t1, t2, key);
                    }
                #pragma unroll
                for (int off = 4; off <= 16; off <<= 1) {
                    ull r0 = __shfl_xor_sync(0xffffffffu, t0, off);
                    ull r1 = __shfl_xor_sync(0xffffffffu, t1, off);
                    ull r2 = __shfl_xor_sync(0xffffffffu, t2, off);
                    ins3(t0, t1, t2, r0); ins3(t0, t1, t2, r1); ins3(t0, t1, t2, r2);
                }
                if (lane < 4) {
                    size_t b = ((size_t)nl * 4 + wm) * 3;
                    p_c[b + 0] = t0; p_c[b + 1] = t1; p_c[b + 2] = t2;
                }
            }
    }

    __syncthreads();
    if (t < 128) {
        ull t0 = ~0ull, t1 = ~0ull, t2 = ~0ull;
        #pragma unroll
        for (int g = 0; g < 6; ++g) ins3(t0, t1, t2, p_r[(size_t)t * 6 + g]);
        size_t base = ((size_t)(rowA + t) * NT + bx) * 3;
        g_part[base + 0] = t0; g_part[base + 1] = t1; g_part[base + 2] = t2;
    } else if (bx != by) {
        int n = t - 128;
        ull t0 = ~0ull, t1 = ~0ull, t2 = ~0ull;
        #pragma unroll
        for (int g = 0; g < 12; ++g) ins3(t0, t1, t2, p_c[(size_t)n * 12 + g]);
        size_t base = ((size_t)(rowB + n) * NT + by) * 3;
        g_part[base + 0] = t0; g_part[base + 1] = t1; g_part[base + 2] = t2;
    }
}

__global__ void k_merge() {
    int row  = (blockIdx.x * blockDim.x + threadIdx.x) >> 5;
    int lane = threadIdx.x & 31;
    ull t0 = ~0ull, t1 = ~0ull, t2 = ~0ull;
    size_t base = (size_t)row * (NT * 3);
    for (int p = lane; p < NT * 3; p += 32) ins3(t0, t1, t2, g_part[base + p]);
    #pragma unroll
    for (int off = 16; off; off >>= 1) {
        ull r0 = __shfl_down_sync(0xffffffffu, t0, off);
        ull r1 = __shfl_down_sync(0xffffffffu, t1, off);
        ull r2 = __shfl_down_sync(0xffffffffu, t2, off);
        ins3(t0, t1, t2, r0); ins3(t0, t1, t2, r1); ins3(t0, t1, t2, r2);
    }
    if (lane == 0) {
        g_top3[(size_t)row * 3 + 0] = t0;
        g_top3[(size_t)row * 3 + 1] = t1;
        g_top3[(size_t)row * 3 + 2] = t2;
    }
}

// Cross-entropy: 256 threads = 128 cols x 2 K-halves; 16 rows/block.
__global__ __launch_bounds__(256) void k_loss(const float* __restrict__ x,
                                              const int* __restrict__ y,
                                              const float* __restrict__ W,
                                              const float* __restrict__ b) {
    __shared__ float xs[16][512];
    __shared__ float lgp[16][128];   // partial from K-half 1
    __shared__ float lg[16][128];    // final logits
    int tid  = threadIdx.x;
    int row0 = blockIdx.x * 16;
    int c = tid & 127;
    int half = tid >> 7;

    #pragma unroll
    for (int i = 0; i < 8; ++i) {
        int id = tid + 256 * i;       // 2048 float4
        int r  = id >> 7;
        int q  = id & 127;
        float4 v = *(const float4*)&x[(size_t)(row0 + r) * DD + q * 4];
        *(float4*)&xs[r][q * 4] = v;
    }
    __syncthreads();

    float acc[16];
    #pragma unroll
    for (int r = 0; r < 16; r++) acc[r] = 0.f;
    int kbase = half * 256;
    #pragma unroll 4
    for (int d0 = 0; d0 < 256; d0 += 4) {
        int d = kbase + d0;
        float w0 = W[(d + 0) * CC + c];
        float w1 = W[(d + 1) * CC + c];
        float w2 = W[(d + 2) * CC + c];
        float w3 = W[(d + 3) * CC + c];
        #pragma unroll
        for (int r = 0; r < 16; r++) {
            float4 xv = *(const float4*)&xs[r][d];
            acc[r] = fmaf(xv.x, w0, acc[r]);
            acc[r] = fmaf(xv.y, w1, acc[r]);
            acc[r] = fmaf(xv.z, w2, acc[r]);
            acc[r] = fmaf(xv.w, w3, acc[r]);
        }
    }
    if (half == 1) {
        #pragma unroll
        for (int r = 0; r < 16; r++) lgp[r][c] = acc[r];
    }
    __syncthreads();
    if (half == 0) {
        float bc = b[c];
        #pragma unroll
        for (int r = 0; r < 16; r++) lg[r][c] = acc[r] + lgp[r][c] + bc;
    }
    __syncthreads();

    // softmax: 8 warps, 2 rows each
    int w = tid >> 5, lane = tid & 31;
    #pragma unroll
    for (int s = 0; s < 2; ++s) {
        int r = w * 2 + s;
        float l0 = lg[r][lane], l1 = lg[r][lane + 32], l2 = lg[r][lane + 64], l3 = lg[r][lane + 96];
        float mx = fmaxf(fmaxf(l0, l1), fmaxf(l2, l3));
        #pragma unroll
        for (int off = 16; off; off >>= 1) mx = fmaxf(mx, __shfl_xor_sync(0xffffffffu, mx, off));
        float se = expf(l0 - mx) + expf(l1 - mx) + expf(l2 - mx) + expf(l3 - mx);
        #pragma unroll
        for (int off = 16; off; off >>= 1) se += __shfl_xor_sync(0xffffffffu, se, off);
        if (lane == 0) {
            int lab  = y[row0 + r];
            float ll = lg[r][lab];
            atomicAdd(&g_loss, (mx + logf(se) - ll) * (1.0f / NN));
        }
    }
}

__global__ void k_reg(const int* __restrict__ y, const float* __restrict__ yo) {
    int row  = (blockIdx.x * blockDim.x + threadIdx.x) >> 5;
    int lane = threadIdx.x & 31;
    ull k0 = g_top3[(size_t)row * 3 + 0];
    ull k1 = g_top3[(size_t)row * 3 + 1];
    ull k2 = g_top3[(size_t)row * 3 + 2];
    int yi = y[row];
    float acc = 0.f;
    #pragma unroll
    for (int tq = 0; tq < 3; ++tq) {
        ull kt = (tq == 0) ? k0 : (tq == 1) ? k1 : k2;
        int n = (int)(kt & 0xffffffffu);
        float e2;
        bool use = true;
        if      (n == 0) e2 = __uint_as_float((unsigned)(k0 >> 32));
        else if (n == 1) e2 = __uint_as_float((unsigned)(k1 >> 32));
        else if (n == 2) e2 = __uint_as_float((unsigned)(k2 >> 32));
        else { e2 = 0.f; use = false; }  // exp(-d_sorted[i, n>=3]) <= ~2e-12: drop
        if (!use) continue;
        if (y[n] != yi) continue;
        float s = 0.f;
        #pragma unroll
        for (int q = 0; q < 4; ++q) {
            float dv = yo[(size_t)row * CC + lane + 32 * q] - yo[(size_t)n * CC + lane + 32 * q];
            s = fmaf(dv, dv, s);
        }
        #pragma unroll
        for (int off = 16; off; off >>= 1) s += __shfl_xor_sync(0xffffffffu, s, off);
        float dyv = sqrtf(s);
        acc += dyv * expf(-sqrtf(e2));
    }
    if (lane == 0) atomicAdd(&g_reg, acc);
}

__global__ void k_final(float* out) { out[0] = g_loss + ALPHA_ * g_reg; }

extern "C" void kernel_launch(void* const* d_in, const int* in_sizes, int n_in,
                              void* d_out, int out_size) {
    (void)in_sizes; (void)n_in; (void)out_size;
    const float* x  = (const float*)d_in[0];
    const int*   y  = (const int*)d_in[1];
    const float* yo = (const float*)d_in[2];
    const float* W  = (const float*)d_in[3];
    const float* b  = (const float*)d_in[4];
    float* out = (float*)d_out;

    k_init<<<1, 1>>>();
    k_cvt_sq<<<NN / 8, 256>>>(x);
    k_loss<<<NN / 16, 256>>>(x, y, W, b);
    k_mma_top3<<<NT * (NT + 1) / 2, 256>>>();
    k_merge<<<NN / 8, 256>>>();
    k_reg<<<NN / 8, 256>>>(y, yo);
    k_final<<<1, 1>>>(out);
}

// round 10
// speedup vs baseline: 2.9246x; 1.0435x over previous
#include <cuda_runtime.h>
#include <cuda_bf16.h>
#include <math.h>

#define NN 4096
#define DD 512
#define CC 128
#define ALPHA_ 0.0005f
#define NT 32

typedef unsigned long long ull;

__device__ float g_sq[NN];
__device__ ull   g_part[NN * NT * 3];
__device__ ull   g_top3[NN * 3];
__device__ float g_loss;
__device__ float g_reg;
__device__ __nv_bfloat16 g_xhi[NN * DD];
__device__ __nv_bfloat16 g_xlo[NN * DD];

__device__ __forceinline__ void ins3(ull &a0, ull &a1, ull &a2, ull k) {
    if (k < a2) a2 = k;
    if (a2 < a1) { ull t = a1; a1 = a2; a2 = t; }
    if (a1 < a0) { ull t = a0; a0 = a1; a1 = t; }
}

__device__ __forceinline__ unsigned smem_u32(const void* p) {
    unsigned a;
    asm("{ .reg .u64 t; cvta.to.shared.u64 t, %1; cvt.u32.u64 %0, t; }" : "=r"(a) : "l"(p));
    return a;
}

#define LDSMX4(r0, r1, r2, r3, addr) \
    asm volatile("ldmatrix.sync.aligned.m8n8.x4.shared.b16 {%0,%1,%2,%3}, [%4];" \
        : "=r"(r0), "=r"(r1), "=r"(r2), "=r"(r3) : "r"(addr))

#define MMA16816(d, a, b) \
    asm volatile("mma.sync.aligned.m16n8k16.row.col.f32.bf16.bf16.f32 " \
        "{%0,%1,%2,%3}, {%4,%5,%6,%7}, {%8,%9}, {%0,%1,%2,%3};" \
        : "+f"((d)[0]), "+f"((d)[1]), "+f"((d)[2]), "+f"((d)[3]) \
        : "r"((a)[0]), "r"((a)[1]), "r"((a)[2]), "r"((a)[3]), "r"((b)[0]), "r"((b)[1]))

__global__ void k_init() { g_loss = 0.f; g_reg = 0.f; }

// fused: bf16 hi/lo split + per-row squared norm (one pass over x)
__global__ void k_cvt_sq(const float* __restrict__ x) {
    int row  = (blockIdx.x * blockDim.x + threadIdx.x) >> 5;
    int lane = threadIdx.x & 31;
    float s = 0.f;
    #pragma unroll
    for (int q = 0; q < 4; ++q) {
        size_t i = (size_t)row * DD + lane * 4 + q * 128;
        float4 v = *(const float4*)(x + i);
        s = fmaf(v.x, v.x, s); s = fmaf(v.y, v.y, s);
        s = fmaf(v.z, v.z, s); s = fmaf(v.w, v.w, s);
        __nv_bfloat16 h0 = __float2bfloat16(v.x), h1 = __float2bfloat16(v.y);
        __nv_bfloat16 h2 = __float2bfloat16(v.z), h3 = __float2bfloat16(v.w);
        __nv_bfloat16 l0 = __float2bfloat16(v.x - __bfloat162float(h0));
        __nv_bfloat16 l1 = __float2bfloat16(v.y - __bfloat162float(h1));
        __nv_bfloat16 l2 = __float2bfloat16(v.z - __bfloat162float(h2));
        __nv_bfloat16 l3 = __float2bfloat16(v.w - __bfloat162float(h3));
        __nv_bfloat162 hA; hA.x = h0; hA.y = h1;
        __nv_bfloat162 hB; hB.x = h2; hB.y = h3;
        __nv_bfloat162 lA; lA.x = l0; lA.y = l1;
        __nv_bfloat162 lB; lB.x = l2; lB.y = l3;
        *(__nv_bfloat162*)(g_xhi + i)     = hA;
        *(__nv_bfloat162*)(g_xhi + i + 2) = hB;
        *(__nv_bfloat162*)(g_xlo + i)     = lA;
        *(__nv_bfloat162*)(g_xlo + i + 2) = lB;
    }
    #pragma unroll
    for (int off = 16; off; off >>= 1) s += __shfl_down_sync(0xffffffffu, s, off);
    if (lane == 0) g_sq[row] = s;
}

// ---------------- cp.async double-buffered mma.sync GEMM + fused dual top-3 ----------------
// dyn smem: [0:512) sqA, [512:1024) sqB, [1024: +2*40960) buffers
// buffer b tile t (0 Ahi,1 Alo,2 Bhi,3 Blo): 1024 + b*40960 + t*10240, rows pitch 80B
__global__ __launch_bounds__(256, 2) void k_mma_top3() {
    extern __shared__ __align__(16) char dsm[];
    float* s_sqA = (float*)dsm;
    float* s_sqB = (float*)(dsm + 512);
    const unsigned BUF0 = 1024, BUFSZ = 40960, TILESZ = 10240;

    int t = threadIdx.x, lane = t & 31, wid = t >> 5;
    int wm = wid >> 1, wn = wid & 1;
    int mbase = wm * 32, nbase = wn * 64;

    int id = blockIdx.x, by = 0;
    while (id >= NT - by) { id -= NT - by; by++; }
    int bx = by + id;
    int rowA = by * 128, rowB = bx * 128;

    if (t < 128) { s_sqA[t] = g_sq[rowA + t]; s_sqB[t] = g_sq[rowB + t]; }

    unsigned sb = smem_u32(dsm);

    // per-thread cp.async assignments: c in 0..7, tile = c&3
    const char* srcPtr[8];
    unsigned dstOff[8];
    #pragma unroll
    for (int c = 0; c < 8; ++c) {
        int tile = c & 3, part = c >> 2;
        int i2 = t + 256 * part;          // 0..511
        int r = i2 >> 2, q = i2 & 3;
        const char* base = (tile & 1) ? (const char*)g_xlo : (const char*)g_xhi;
        int rowT = (tile >= 2) ? rowB : rowA;
        srcPtr[c] = base + ((size_t)(rowT + r) << 10) + q * 16;
        dstOff[c] = BUF0 + tile * TILESZ + r * 80 + q * 16;
    }

    float acc[2][8][4];
    #pragma unroll
    for (int i = 0; i < 2; i++)
        #pragma unroll
        for (int j = 0; j < 8; j++)
            #pragma unroll
            for (int k = 0; k < 4; k++) acc[i][j][k] = 0.f;

    unsigned aOff = ((mbase + (lane & 15)) * 40 + (lane >> 4) * 8) * 2;
    unsigned bOff = ((nbase + (lane & 7) + ((lane >> 4) << 3)) * 40 + ((lane >> 3) & 1) * 8) * 2;

    // prologue: stage 0 into buffer 0
    #pragma unroll
    for (int c = 0; c < 8; ++c) {
        asm volatile("cp.async.cg.shared.global [%0], [%1], 16;"
            :: "r"(sb + dstOff[c]), "l"(srcPtr[c]) : "memory");
        srcPtr[c] += 64;
    }
    asm volatile("cp.async.commit_group;" ::: "memory");

    for (int s = 0; s < 16; ++s) {
        if (s < 15) {
            unsigned bofs = ((s + 1) & 1) * BUFSZ;
            #pragma unroll
            for (int c = 0; c < 8; ++c) {
                asm volatile("cp.async.cg.shared.global [%0], [%1], 16;"
                    :: "r"(sb + dstOff[c] + bofs), "l"(srcPtr[c]) : "memory");
                srcPtr[c] += 64;
            }
            asm volatile("cp.async.commit_group;" ::: "memory");
            asm volatile("cp.async.wait_group 1;" ::: "memory");
        } else {
            asm volatile("cp.async.wait_group 0;" ::: "memory");
        }
        __syncthreads();

        unsigned bb = sb + BUF0 + (s & 1) * BUFSZ;
        unsigned baseAh = bb, baseAl = bb + TILESZ, baseBh = bb + 2 * TILESZ, baseBl = bb + 3 * TILESZ;

        #pragma unroll
        for (int kh = 0; kh < 2; ++kh) {
            unsigned ko = kh * 32;
            unsigned aH[2][4], aL[2][4], bb2[8][2];
            LDSMX4(aH[0][0], aH[0][1], aH[0][2], aH[0][3], baseAh + aOff + ko);
            LDSMX4(aH[1][0], aH[1][1], aH[1][2], aH[1][3], baseAh + aOff + 16 * 80 + ko);
            LDSMX4(aL[0][0], aL[0][1], aL[0][2], aL[0][3], baseAl + aOff + ko);
            LDSMX4(aL[1][0], aL[1][1], aL[1][2], aL[1][3], baseAl + aOff + 16 * 80 + ko);
            #pragma unroll
            for (int g = 0; g < 4; ++g)
                LDSMX4(bb2[2*g][0], bb2[2*g][1], bb2[2*g+1][0], bb2[2*g+1][1],
                       baseBh + bOff + g * 16 * 80 + ko);
            #pragma unroll
            for (int mt = 0; mt < 2; ++mt)
                #pragma unroll
                for (int nt = 0; nt < 8; ++nt) {
                    MMA16816(acc[mt][nt], aH[mt], bb2[nt]);
                    MMA16816(acc[mt][nt], aL[mt], bb2[nt]);
                }
            #pragma unroll
            for (int g = 0; g < 4; ++g)
                LDSMX4(bb2[2*g][0], bb2[2*g][1], bb2[2*g+1][0], bb2[2*g+1][1],
                       baseBl + bOff + g * 16 * 80 + ko);
            #pragma unroll
            for (int mt = 0; mt < 2; ++mt)
                #pragma unroll
                for (int nt = 0; nt < 8; ++nt)
                    MMA16816(acc[mt][nt], aH[mt], bb2[nt]);
        }
        __syncthreads();
    }

    const float* sqa = s_sqA;
    const float* sqb = s_sqB;
    #pragma unroll
    for (int mt = 0; mt < 2; ++mt)
        #pragma unroll
        for (int nt = 0; nt < 8; ++nt)
            #pragma unroll
            for (int c4 = 0; c4 < 4; ++c4) {
                int h = c4 >> 1, c = c4 & 1;
                int ml = mbase + mt * 16 + (lane >> 2) + h * 8;
                int nl = nbase + nt * 8 + 2 * (lane & 3) + c;
                float d2 = sqa[ml] + sqb[nl] - 2.f * acc[mt][nt][c4];
                float e2 = d2 > 0.f ? d2 : 0.f;
                if (rowA + ml == rowB + nl) e2 = 0.f;
                acc[mt][nt][c4] = e2;
            }

    ull* p_r = (ull*)(dsm + BUF0);          // [128][2][3] = 6 KB
    ull* p_c = (ull*)(dsm + BUF0 + 8192);   // [128][4][3] = 12 KB

    #pragma unroll
    for (int mt = 0; mt < 2; ++mt)
        #pragma unroll
        for (int h = 0; h < 2; ++h) {
            int ml = mbase + mt * 16 + (lane >> 2) + h * 8;
            ull t0 = ~0ull, t1 = ~0ull, t2 = ~0ull;
            #pragma unroll
            for (int nt = 0; nt < 8; ++nt)
                #pragma unroll
                for (int c = 0; c < 2; ++c) {
                    int nl = nbase + nt * 8 + 2 * (lane & 3) + c;
                    ull key = ((ull)__float_as_uint(acc[mt][nt][2 * h + c]) << 32) | (unsigned)(rowB + nl);
                    ins3(t0, t1, t2, key);
                }
            #pragma unroll
            for (int off = 1; off <= 2; off <<= 1) {
                ull r0 = __shfl_xor_sync(0xffffffffu, t0, off);
                ull r1 = __shfl_xor_sync(0xffffffffu, t1, off);
                ull r2 = __shfl_xor_sync(0xffffffffu, t2, off);
                ins3(t0, t1, t2, r0); ins3(t0, t1, t2, r1); ins3(t0, t1, t2, r2);
            }
            if ((lane & 3) == 0) {
                size_t b = ((size_t)ml * 2 + wn) * 3;
                p_r[b + 0] = t0; p_r[b + 1] = t1; p_r[b + 2] = t2;
            }
        }

    if (bx != by) {
        #pragma unroll
        for (int nt = 0; nt < 8; ++nt)
            #pragma unroll
            for (int c = 0; c < 2; ++c) {
                int nl = nbase + nt * 8 + 2 * (lane & 3) + c;
                ull t0 = ~0ull, t1 = ~0ull, t2 = ~0ull;
                #pragma unroll
                for (int mt = 0; mt < 2; ++mt)
                    #pragma unroll
                    for (int h = 0; h < 2; ++h) {
                        int ml = mbase + mt * 16 + (lane >> 2) + h * 8;
                        ull key = ((ull)__float_as_uint(acc[mt][nt][2 * h + c]) << 32) | (unsigned)(rowA + ml);
                        ins3(t0, t1, t2, key);
                    }
                #pragma unroll
                for (int off = 4; off <= 16; off <<= 1) {
                    ull r0 = __shfl_xor_sync(0xffffffffu, t0, off);
                    ull r1 = __shfl_xor_sync(0xffffffffu, t1, off);
                    ull r2 = __shfl_xor_sync(0xffffffffu, t2, off);
                    ins3(t0, t1, t2, r0); ins3(t0, t1, t2, r1); ins3(t0, t1, t2, r2);
                }
                if (lane < 4) {
                    size_t b = ((size_t)nl * 4 + wm) * 3;
                    p_c[b + 0] = t0; p_c[b + 1] = t1; p_c[b + 2] = t2;
                }
            }
    }

    __syncthreads();
    if (t < 128) {
        ull t0 = ~0ull, t1 = ~0ull, t2 = ~0ull;
        #pragma unroll
        for (int g = 0; g < 6; ++g) ins3(t0, t1, t2, p_r[(size_t)t * 6 + g]);
        size_t base = ((size_t)(rowA + t) * NT + bx) * 3;
        g_part[base + 0] = t0; g_part[base + 1] = t1; g_part[base + 2] = t2;
    } else if (bx != by) {
        int n = t - 128;
        ull t0 = ~0ull, t1 = ~0ull, t2 = ~0ull;
        #pragma unroll
        for (int g = 0; g < 12; ++g) ins3(t0, t1, t2, p_c[(size_t)n * 12 + g]);
        size_t base = ((size_t)(rowB + n) * NT + by) * 3;
        g_part[base + 0] = t0; g_part[base + 1] = t1; g_part[base + 2] = t2;
    }
}

__global__ void k_merge() {
    int row  = (blockIdx.x * blockDim.x + threadIdx.x) >> 5;
    int lane = threadIdx.x & 31;
    ull t0 = ~0ull, t1 = ~0ull, t2 = ~0ull;
    size_t base = (size_t)row * (NT * 3);
    for (int p = lane; p < NT * 3; p += 32) ins3(t0, t1, t2, g_part[base + p]);
    #pragma unroll
    for (int off = 16; off; off >>= 1) {
        ull r0 = __shfl_down_sync(0xffffffffu, t0, off);
        ull r1 = __shfl_down_sync(0xffffffffu, t1, off);
        ull r2 = __shfl_down_sync(0xffffffffu, t2, off);
        ins3(t0, t1, t2, r0); ins3(t0, t1, t2, r1); ins3(t0, t1, t2, r2);
    }
    if (lane == 0) {
        g_top3[(size_t)row * 3 + 0] = t0;
        g_top3[(size_t)row * 3 + 1] = t1;
        g_top3[(size_t)row * 3 + 2] = t2;
    }
}

// Cross-entropy: 256 threads = 128 cols x 2 K-halves; 16 rows/block.
__global__ __launch_bounds__(256) void k_loss(const float* __restrict__ x,
                                              const int* __restrict__ y,
                                              const float* __restrict__ W,
                                              const float* __restrict__ b) {
    __shared__ float xs[16][512];
    __shared__ float lgp[16][128];
    __shared__ float lg[16][128];
    int tid  = threadIdx.x;
    int row0 = blockIdx.x * 16;
    int c = tid & 127;
    int half = tid >> 7;

    #pragma unroll
    for (int i = 0; i < 8; ++i) {
        int id = tid + 256 * i;
        int r  = id >> 7;
        int q  = id & 127;
        float4 v = *(const float4*)&x[(size_t)(row0 + r) * DD + q * 4];
        *(float4*)&xs[r][q * 4] = v;
    }
    __syncthreads();

    float acc[16];
    #pragma unroll
    for (int r = 0; r < 16; r++) acc[r] = 0.f;
    int kbase = half * 256;
    #pragma unroll 4
    for (int d0 = 0; d0 < 256; d0 += 4) {
        int d = kbase + d0;
        float w0 = W[(d + 0) * CC + c];
        float w1 = W[(d + 1) * CC + c];
        float w2 = W[(d + 2) * CC + c];
        float w3 = W[(d + 3) * CC + c];
        #pragma unroll
        for (int r = 0; r < 16; r++) {
            float4 xv = *(const float4*)&xs[r][d];
            acc[r] = fmaf(xv.x, w0, acc[r]);
            acc[r] = fmaf(xv.y, w1, acc[r]);
            acc[r] = fmaf(xv.z, w2, acc[r]);
            acc[r] = fmaf(xv.w, w3, acc[r]);
        }
    }
    if (half == 1) {
        #pragma unroll
        for (int r = 0; r < 16; r++) lgp[r][c] = acc[r];
    }
    __syncthreads();
    if (half == 0) {
        float bc = b[c];
        #pragma unroll
        for (int r = 0; r < 16; r++) lg[r][c] = acc[r] + lgp[r][c] + bc;
    }
    __syncthreads();

    int w = tid >> 5, lane = tid & 31;
    #pragma unroll
    for (int s = 0; s < 2; ++s) {
        int r = w * 2 + s;
        float l0 = lg[r][lane], l1 = lg[r][lane + 32], l2 = lg[r][lane + 64], l3 = lg[r][lane + 96];
        float mx = fmaxf(fmaxf(l0, l1), fmaxf(l2, l3));
        #pragma unroll
        for (int off = 16; off; off >>= 1) mx = fmaxf(mx, __shfl_xor_sync(0xffffffffu, mx, off));
        float se = expf(l0 - mx) + expf(l1 - mx) + expf(l2 - mx) + expf(l3 - mx);
        #pragma unroll
        for (int off = 16; off; off >>= 1) se += __shfl_xor_sync(0xffffffffu, se, off);
        if (lane == 0) {
            int lab  = y[row0 + r];
            float ll = lg[r][lab];
            atomicAdd(&g_loss, (mx + logf(se) - ll) * (1.0f / NN));
        }
    }
}

__global__ void k_reg(const int* __restrict__ y, const float* __restrict__ yo) {
    int row  = (blockIdx.x * blockDim.x + threadIdx.x) >> 5;
    int lane = threadIdx.x & 31;
    ull k0 = g_top3[(size_t)row * 3 + 0];
    ull k1 = g_top3[(size_t)row * 3 + 1];
    ull k2 = g_top3[(size_t)row * 3 + 2];
    int yi = y[row];
    float acc = 0.f;
    #pragma unroll
    for (int tq = 0; tq < 3; ++tq) {
        ull kt = (tq == 0) ? k0 : (tq == 1) ? k1 : k2;
        int n = (int)(kt & 0xffffffffu);
        float e2;
        bool use = true;
        if      (n == 0) e2 = __uint_as_float((unsigned)(k0 >> 32));
        else if (n == 1) e2 = __uint_as_float((unsigned)(k1 >> 32));
        else if (n == 2) e2 = __uint_as_float((unsigned)(k2 >> 32));
        else { e2 = 0.f; use = false; }  // exp(-d_sorted[i, n>=3]) <= ~2e-12: drop
        if (!use) continue;
        if (y[n] != yi) continue;
        float s = 0.f;
        #pragma unroll
        for (int q = 0; q < 4; ++q) {
            float dv = yo[(size_t)row * CC + lane + 32 * q] - yo[(size_t)n * CC + lane + 32 * q];
            s = fmaf(dv, dv, s);
        }
        #pragma unroll
        for (int off = 16; off; off >>= 1) s += __shfl_xor_sync(0xffffffffu, s, off);
        float dyv = sqrtf(s);
        acc += dyv * expf(-sqrtf(e2));
    }
    if (lane == 0) atomicAdd(&g_reg, acc);
}

__global__ void k_final(float* out) { out[0] = g_loss + ALPHA_ * g_reg; }

extern "C" void kernel_launch(void* const* d_in, const int* in_sizes, int n_in,
                              void* d_out, int out_size) {
    (void)in_sizes; (void)n_in; (void)out_size;
    const float* x  = (const float*)d_in[0];
    const int*   y  = (const int*)d_in[1];
    const float* yo = (const float*)d_in[2];
    const float* W  = (const float*)d_in[3];
    const float* b  = (const float*)d_in[4];
    float* out = (float*)d_out;

    const int DYN_SMEM = 1024 + 2 * 40960;   // 82944
    cudaFuncSetAttribute(k_mma_top3, cudaFuncAttributeMaxDynamicSharedMemorySize, DYN_SMEM);

    k_init<<<1, 1>>>();
    k_cvt_sq<<<NN / 8, 256>>>(x);
    k_loss<<<NN / 16, 256>>>(x, y, W, b);
    k_mma_top3<<<NT * (NT + 1) / 2, 256, DYN_SMEM>>>();
    k_merge<<<NN / 8, 256>>>();
    k_reg<<<NN / 8, 256>>>(y, yo);
    k_final<<<1, 1>>>(out);
}

// round 11
// speedup vs baseline: 4.1191x; 1.4084x over previous
#include <cuda_runtime.h>
#include <cuda_bf16.h>
#include <math.h>

#define NN 4096
#define DD 512
#define CC 128
#define ALPHA_ 0.0005f
#define NT 32

typedef unsigned long long ull;

__device__ float g_sq[NN];
__device__ ull   g_part[NN * NT * 3];
__device__ ull   g_top3[NN * 3];
__device__ float g_loss;
__device__ float g_reg;
__device__ __nv_bfloat16 g_xhi[NN * DD];

__device__ __forceinline__ void ins3(ull &a0, ull &a1, ull &a2, ull k) {
    if (k < a2) a2 = k;
    if (a2 < a1) { ull t = a1; a1 = a2; a2 = t; }
    if (a1 < a0) { ull t = a0; a0 = a1; a1 = t; }
}

__device__ __forceinline__ unsigned smem_u32(const void* p) {
    unsigned a;
    asm("{ .reg .u64 t; cvta.to.shared.u64 t, %1; cvt.u32.u64 %0, t; }" : "=r"(a) : "l"(p));
    return a;
}

#define LDSMX4(r0, r1, r2, r3, addr) \
    asm volatile("ldmatrix.sync.aligned.m8n8.x4.shared.b16 {%0,%1,%2,%3}, [%4];" \
        : "=r"(r0), "=r"(r1), "=r"(r2), "=r"(r3) : "r"(addr))

#define MMA16816(d, a, b) \
    asm volatile("mma.sync.aligned.m16n8k16.row.col.f32.bf16.bf16.f32 " \
        "{%0,%1,%2,%3}, {%4,%5,%6,%7}, {%8,%9}, {%0,%1,%2,%3};" \
        : "+f"((d)[0]), "+f"((d)[1]), "+f"((d)[2]), "+f"((d)[3]) \
        : "r"((a)[0]), "r"((a)[1]), "r"((a)[2]), "r"((a)[3]), "r"((b)[0]), "r"((b)[1]))

__global__ void k_init() { g_loss = 0.f; g_reg = 0.f; }

// fused: bf16 hi cast + per-row squared norm (one pass over x)
__global__ void k_cvt_sq(const float* __restrict__ x) {
    int row  = (blockIdx.x * blockDim.x + threadIdx.x) >> 5;
    int lane = threadIdx.x & 31;
    float s = 0.f;
    #pragma unroll
    for (int q = 0; q < 4; ++q) {
        size_t i = (size_t)row * DD + lane * 4 + q * 128;
        float4 v = *(const float4*)(x + i);
        s = fmaf(v.x, v.x, s); s = fmaf(v.y, v.y, s);
        s = fmaf(v.z, v.z, s); s = fmaf(v.w, v.w, s);
        __nv_bfloat162 hA; hA.x = __float2bfloat16(v.x); hA.y = __float2bfloat16(v.y);
        __nv_bfloat162 hB; hB.x = __float2bfloat16(v.z); hB.y = __float2bfloat16(v.w);
        *(__nv_bfloat162*)(g_xhi + i)     = hA;
        *(__nv_bfloat162*)(g_xhi + i + 2) = hB;
    }
    #pragma unroll
    for (int off = 16; off; off >>= 1) s += __shfl_down_sync(0xffffffffu, s, off);
    if (lane == 0) g_sq[row] = s;
}

// ---------------- 3-stage cp.async mma.sync GEMM (hi only) + fused dual top-3 ----------------
// dyn smem: [0:512) sqA, [512:1024) sqB, [1024: +3*20480) buffers
// buffer b: tile 0 = A, tile 1 = B; each 128 rows x 32 bf16, pitch 80B
__global__ __launch_bounds__(256, 2) void k_mma_top3() {
    extern __shared__ __align__(16) char dsm[];
    float* s_sqA = (float*)dsm;
    float* s_sqB = (float*)(dsm + 512);
    const unsigned BUF0 = 1024, BUFSZ = 20480, TILESZ = 10240;

    int t = threadIdx.x, lane = t & 31, wid = t >> 5;
    int wm = wid >> 1, wn = wid & 1;
    int mbase = wm * 32, nbase = wn * 64;

    int id = blockIdx.x, by = 0;
    while (id >= NT - by) { id -= NT - by; by++; }
    int bx = by + id;
    int rowA = by * 128, rowB = bx * 128;

    if (t < 128) { s_sqA[t] = g_sq[rowA + t]; s_sqB[t] = g_sq[rowB + t]; }

    unsigned sb = smem_u32(dsm);

    // per-thread cp.async assignments: c in 0..3, tile = c&1 (0=A,1=B)
    const char* srcPtr[4];
    unsigned dstOff[4];
    #pragma unroll
    for (int c = 0; c < 4; ++c) {
        int tile = c & 1, part = c >> 1;
        int i2 = t + 256 * part;          // 0..511
        int r = i2 >> 2, q = i2 & 3;
        int rowT = tile ? rowB : rowA;
        srcPtr[c] = (const char*)g_xhi + ((size_t)(rowT + r) << 10) + q * 16;
        dstOff[c] = BUF0 + tile * TILESZ + r * 80 + q * 16;
    }

    float acc[2][8][4];
    #pragma unroll
    for (int i = 0; i < 2; i++)
        #pragma unroll
        for (int j = 0; j < 8; j++)
            #pragma unroll
            for (int k = 0; k < 4; k++) acc[i][j][k] = 0.f;

    unsigned aOff = ((mbase + (lane & 15)) * 40 + (lane >> 4) * 8) * 2;
    unsigned bOff = ((nbase + (lane & 7) + ((lane >> 4) << 3)) * 40 + ((lane >> 3) & 1) * 8) * 2;

    // prologue: stage 0 -> buf0, stage 1 -> buf1
    #pragma unroll
    for (int c = 0; c < 4; ++c)
        asm volatile("cp.async.cg.shared.global [%0], [%1], 16;"
            :: "r"(sb + dstOff[c]), "l"(srcPtr[c]) : "memory");
    asm volatile("cp.async.commit_group;" ::: "memory");
    #pragma unroll
    for (int c = 0; c < 4; ++c)
        asm volatile("cp.async.cg.shared.global [%0], [%1], 16;"
            :: "r"(sb + dstOff[c] + BUFSZ), "l"(srcPtr[c] + 64) : "memory");
    asm volatile("cp.async.commit_group;" ::: "memory");

    for (int s = 0; s < 16; ++s) {
        if (s < 15) asm volatile("cp.async.wait_group 1;" ::: "memory");
        else        asm volatile("cp.async.wait_group 0;" ::: "memory");
        __syncthreads();

        if (s + 2 < 16) {
            unsigned bofs = ((s + 2) % 3) * BUFSZ;
            #pragma unroll
            for (int c = 0; c < 4; ++c)
                asm volatile("cp.async.cg.shared.global [%0], [%1], 16;"
                    :: "r"(sb + dstOff[c] + bofs), "l"(srcPtr[c] + (size_t)(s + 2) * 64) : "memory");
            asm volatile("cp.async.commit_group;" ::: "memory");
        }

        unsigned bb = sb + BUF0 + (s % 3) * BUFSZ;
        unsigned baseA = bb, baseB = bb + TILESZ;

        #pragma unroll
        for (int kh = 0; kh < 2; ++kh) {
            unsigned ko = kh * 32;
            unsigned aH[2][4], bb2[8][2];
            LDSMX4(aH[0][0], aH[0][1], aH[0][2], aH[0][3], baseA + aOff + ko);
            LDSMX4(aH[1][0], aH[1][1], aH[1][2], aH[1][3], baseA + aOff + 16 * 80 + ko);
            #pragma unroll
            for (int g = 0; g < 4; ++g)
                LDSMX4(bb2[2*g][0], bb2[2*g][1], bb2[2*g+1][0], bb2[2*g+1][1],
                       baseB + bOff + g * 16 * 80 + ko);
            #pragma unroll
            for (int mt = 0; mt < 2; ++mt)
                #pragma unroll
                for (int nt = 0; nt < 8; ++nt)
                    MMA16816(acc[mt][nt], aH[mt], bb2[nt]);
        }
    }
    __syncthreads();   // all warps out of the mainloop before overlaying buffers

    const float* sqa = s_sqA;
    const float* sqb = s_sqB;
    #pragma unroll
    for (int mt = 0; mt < 2; ++mt)
        #pragma unroll
        for (int nt = 0; nt < 8; ++nt)
            #pragma unroll
            for (int c4 = 0; c4 < 4; ++c4) {
                int h = c4 >> 1, c = c4 & 1;
                int ml = mbase + mt * 16 + (lane >> 2) + h * 8;
                int nl = nbase + nt * 8 + 2 * (lane & 3) + c;
                float d2 = sqa[ml] + sqb[nl] - 2.f * acc[mt][nt][c4];
                float e2 = d2 > 0.f ? d2 : 0.f;
                if (rowA + ml == rowB + nl) e2 = 0.f;
                acc[mt][nt][c4] = e2;
            }

    ull* p_r = (ull*)(dsm + BUF0);          // [128][2][3] = 6 KB
    ull* p_c = (ull*)(dsm + BUF0 + 8192);   // [128][4][3] = 12 KB

    #pragma unroll
    for (int mt = 0; mt < 2; ++mt)
        #pragma unroll
        for (int h = 0; h < 2; ++h) {
            int ml = mbase + mt * 16 + (lane >> 2) + h * 8;
            ull t0 = ~0ull, t1 = ~0ull, t2 = ~0ull;
            #pragma unroll
            for (int nt = 0; nt < 8; ++nt)
                #pragma unroll
                for (int c = 0; c < 2; ++c) {
                    int nl = nbase + nt * 8 + 2 * (lane & 3) + c;
                    ull key = ((ull)__float_as_uint(acc[mt][nt][2 * h + c]) << 32) | (unsigned)(rowB + nl);
                    ins3(t0, t1, t2, key);
                }
            #pragma unroll
            for (int off = 1; off <= 2; off <<= 1) {
                ull r0 = __shfl_xor_sync(0xffffffffu, t0, off);
                ull r1 = __shfl_xor_sync(0xffffffffu, t1, off);
                ull r2 = __shfl_xor_sync(0xffffffffu, t2, off);
                ins3(t0, t1, t2, r0); ins3(t0, t1, t2, r1); ins3(t0, t1, t2, r2);
            }
            if ((lane & 3) == 0) {
                size_t b = ((size_t)ml * 2 + wn) * 3;
                p_r[b + 0] = t0; p_r[b + 1] = t1; p_r[b + 2] = t2;
            }
        }

    if (bx != by) {
        #pragma unroll
        for (int nt = 0; nt < 8; ++nt)
            #pragma unroll
            for (int c = 0; c < 2; ++c) {
                int nl = nbase + nt * 8 + 2 * (lane & 3) + c;
                ull t0 = ~0ull, t1 = ~0ull, t2 = ~0ull;
                #pragma unroll
                for (int mt = 0; mt < 2; ++mt)
                    #pragma unroll
                    for (int h = 0; h < 2; ++h) {
                        int ml = mbase + mt * 16 + (lane >> 2) + h * 8;
                        ull key = ((ull)__float_as_uint(acc[mt][nt][2 * h + c]) << 32) | (unsigned)(rowA + ml);
                        ins3(t0, t1, t2, key);
                    }
                #pragma unroll
                for (int off = 4; off <= 16; off <<= 1) {
                    ull r0 = __shfl_xor_sync(0xffffffffu, t0, off);
                    ull r1 = __shfl_xor_sync(0xffffffffu, t1, off);
                    ull r2 = __shfl_xor_sync(0xffffffffu, t2, off);
                    ins3(t0, t1, t2, r0); ins3(t0, t1, t2, r1); ins3(t0, t1, t2, r2);
                }
                if (lane < 4) {
                    size_t b = ((size_t)nl * 4 + wm) * 3;
                    p_c[b + 0] = t0; p_c[b + 1] = t1; p_c[b + 2] = t2;
                }
            }
    }

    __syncthreads();
    if (t < 128) {
        ull t0 = ~0ull, t1 = ~0ull, t2 = ~0ull;
        #pragma unroll
        for (int g = 0; g < 6; ++g) ins3(t0, t1, t2, p_r[(size_t)t * 6 + g]);
        size_t base = ((size_t)(rowA + t) * NT + bx) * 3;
        g_part[base + 0] = t0; g_part[base + 1] = t1; g_part[base + 2] = t2;
    } else if (bx != by) {
        int n = t - 128;
        ull t0 = ~0ull, t1 = ~0ull, t2 = ~0ull;
        #pragma unroll
        for (int g = 0; g < 12; ++g) ins3(t0, t1, t2, p_c[(size_t)n * 12 + g]);
        size_t base = ((size_t)(rowB + n) * NT + by) * 3;
        g_part[base + 0] = t0; g_part[base + 1] = t1; g_part[base + 2] = t2;
    }
}

__global__ void k_merge() {
    int row  = (blockIdx.x * blockDim.x + threadIdx.x) >> 5;
    int lane = threadIdx.x & 31;
    ull t0 = ~0ull, t1 = ~0ull, t2 = ~0ull;
    size_t base = (size_t)row * (NT * 3);
    for (int p = lane; p < NT * 3; p += 32) ins3(t0, t1, t2, g_part[base + p]);
    #pragma unroll
    for (int off = 16; off; off >>= 1) {
        ull r0 = __shfl_down_sync(0xffffffffu, t0, off);
        ull r1 = __shfl_down_sync(0xffffffffu, t1, off);
        ull r2 = __shfl_down_sync(0xffffffffu, t2, off);
        ins3(t0, t1, t2, r0); ins3(t0, t1, t2, r1); ins3(t0, t1, t2, r2);
    }
    if (lane == 0) {
        g_top3[(size_t)row * 3 + 0] = t0;
        g_top3[(size_t)row * 3 + 1] = t1;
        g_top3[(size_t)row * 3 + 2] = t2;
    }
}

// Cross-entropy: 256 threads = 128 cols x 2 K-halves; 16 rows/block.
__global__ __launch_bounds__(256) void k_loss(const float* __restrict__ x,
                                              const int* __restrict__ y,
                                              const float* __restrict__ W,
                                              const float* __restrict__ b) {
    __shared__ float xs[16][512];
    __shared__ float lgp[16][128];
    __shared__ float lg[16][128];
    int tid  = threadIdx.x;
    int row0 = blockIdx.x * 16;
    int c = tid & 127;
    int half = tid >> 7;

    #pragma unroll
    for (int i = 0; i < 8; ++i) {
        int id = tid + 256 * i;
        int r  = id >> 7;
        int q  = id & 127;
        float4 v = *(const float4*)&x[(size_t)(row0 + r) * DD + q * 4];
        *(float4*)&xs[r][q * 4] = v;
    }
    __syncthreads();

    float acc[16];
    #pragma unroll
    for (int r = 0; r < 16; r++) acc[r] = 0.f;
    int kbase = half * 256;
    #pragma unroll 4
    for (int d0 = 0; d0 < 256; d0 += 4) {
        int d = kbase + d0;
        float w0 = W[(d + 0) * CC + c];
        float w1 = W[(d + 1) * CC + c];
        float w2 = W[(d + 2) * CC + c];
        float w3 = W[(d + 3) * CC + c];
        #pragma unroll
        for (int r = 0; r < 16; r++) {
            float4 xv = *(const float4*)&xs[r][d];
            acc[r] = fmaf(xv.x, w0, acc[r]);
            acc[r] = fmaf(xv.y, w1, acc[r]);
            acc[r] = fmaf(xv.z, w2, acc[r]);
            acc[r] = fmaf(xv.w, w3, acc[r]);
        }
    }
    if (half == 1) {
        #pragma unroll
        for (int r = 0; r < 16; r++) lgp[r][c] = acc[r];
    }
    __syncthreads();
    if (half == 0) {
        float bc = b[c];
        #pragma unroll
        for (int r = 0; r < 16; r++) lg[r][c] = acc[r] + lgp[r][c] + bc;
    }
    __syncthreads();

    int w = tid >> 5, lane = tid & 31;
    #pragma unroll
    for (int s = 0; s < 2; ++s) {
        int r = w * 2 + s;
        float l0 = lg[r][lane], l1 = lg[r][lane + 32], l2 = lg[r][lane + 64], l3 = lg[r][lane + 96];
        float mx = fmaxf(fmaxf(l0, l1), fmaxf(l2, l3));
        #pragma unroll
        for (int off = 16; off; off >>= 1) mx = fmaxf(mx, __shfl_xor_sync(0xffffffffu, mx, off));
        float se = expf(l0 - mx) + expf(l1 - mx) + expf(l2 - mx) + expf(l3 - mx);
        #pragma unroll
        for (int off = 16; off; off >>= 1) se += __shfl_xor_sync(0xffffffffu, se, off);
        if (lane == 0) {
            int lab  = y[row0 + r];
            float ll = lg[r][lab];
            atomicAdd(&g_loss, (mx + logf(se) - ll) * (1.0f / NN));
        }
    }
}

__global__ void k_reg(const int* __restrict__ y, const float* __restrict__ yo) {
    int row  = (blockIdx.x * blockDim.x + threadIdx.x) >> 5;
    int lane = threadIdx.x & 31;
    ull k0 = g_top3[(size_t)row * 3 + 0];
    ull k1 = g_top3[(size_t)row * 3 + 1];
    ull k2 = g_top3[(size_t)row * 3 + 2];
    int yi = y[row];
    float acc = 0.f;
    #pragma unroll
    for (int tq = 0; tq < 3; ++tq) {
        ull kt = (tq == 0) ? k0 : (tq == 1) ? k1 : k2;
        int n = (int)(kt & 0xffffffffu);
        float e2;
        bool use = true;
        if      (n == 0) e2 = __uint_as_float((unsigned)(k0 >> 32));
        else if (n == 1) e2 = __uint_as_float((unsigned)(k1 >> 32));
        else if (n == 2) e2 = __uint_as_float((unsigned)(k2 >> 32));
        else { e2 = 0.f; use = false; }  // exp(-d_sorted[i, n>=3]) <= ~2e-12: drop
        if (!use) continue;
        if (y[n] != yi) continue;
        float s = 0.f;
        #pragma unroll
        for (int q = 0; q < 4; ++q) {
            float dv = yo[(size_t)row * CC + lane + 32 * q] - yo[(size_t)n * CC + lane + 32 * q];
            s = fmaf(dv, dv, s);
        }
        #pragma unroll
        for (int off = 16; off; off >>= 1) s += __shfl_xor_sync(0xffffffffu, s, off);
        float dyv = sqrtf(s);
        acc += dyv * expf(-sqrtf(e2));
    }
    if (lane == 0) atomicAdd(&g_reg, acc);
}

__global__ void k_final(float* out) { out[0] = g_loss + ALPHA_ * g_reg; }

extern "C" void kernel_launch(void* const* d_in, const int* in_sizes, int n_in,
                              void* d_out, int out_size) {
    (void)in_sizes; (void)n_in; (void)out_size;
    const float* x  = (const float*)d_in[0];
    const int*   y  = (const int*)d_in[1];
    const float* yo = (const float*)d_in[2];
    const float* W  = (const float*)d_in[3];
    const float* b  = (const float*)d_in[4];
    float* out = (float*)d_out;

    const int DYN_SMEM = 1024 + 3 * 20480;   // 62464
    cudaFuncSetAttribute(k_mma_top3, cudaFuncAttributeMaxDynamicSharedMemorySize, DYN_SMEM);

    k_init<<<1, 1>>>();
    k_cvt_sq<<<NN / 8, 256>>>(x);
    k_loss<<<NN / 16, 256>>>(x, y, W, b);
    k_mma_top3<<<NT * (NT + 1) / 2, 256, DYN_SMEM>>>();
    k_merge<<<NN / 8, 256>>>();
    k_reg<<<NN / 8, 256>>>(y, yo);
    k_final<<<1, 1>>>(out);
}

// round 12
// speedup vs baseline: 5.5301x; 1.3426x over previous
#include <cuda_runtime.h>
#include <cuda_bf16.h>
#include <math.h>

#define NN 4096
#define DD 512
#define CC 128
#define ALPHA_ 0.0005f
#define NT 32
#define KEY_EMPTY __uint_as_float(0x7f7fffffu)

typedef unsigned long long ull;

__device__ float g_sq[NN];
__device__ float g_part[NN * NT * 3];
__device__ float g_top3[NN * 3];
__device__ float g_loss;
__device__ float g_reg;
__device__ __nv_bfloat16 g_xhi[NN * DD];

// insert float-packed key into sorted triple (keep 3 smallest) — 5 FMNMX
__device__ __forceinline__ void ins3f(float &a0, float &a1, float &a2, float k) {
    a2 = fminf(a2, k);
    float lo = fminf(a1, a2), hi = fmaxf(a1, a2);
    a1 = lo; a2 = hi;
    lo = fminf(a0, a1); hi = fmaxf(a0, a1);
    a0 = lo; a1 = hi;
}

__device__ __forceinline__ float packkey(float e2, unsigned idx) {
    return __uint_as_float((__float_as_uint(e2) & 0xFFFFF000u) | idx);
}

__device__ __forceinline__ unsigned smem_u32(const void* p) {
    unsigned a;
    asm("{ .reg .u64 t; cvta.to.shared.u64 t, %1; cvt.u32.u64 %0, t; }" : "=r"(a) : "l"(p));
    return a;
}

#define LDSMX4(r0, r1, r2, r3, addr) \
    asm volatile("ldmatrix.sync.aligned.m8n8.x4.shared.b16 {%0,%1,%2,%3}, [%4];" \
        : "=r"(r0), "=r"(r1), "=r"(r2), "=r"(r3) : "r"(addr))

#define MMA16816(d, a, b) \
    asm volatile("mma.sync.aligned.m16n8k16.row.col.f32.bf16.bf16.f32 " \
        "{%0,%1,%2,%3}, {%4,%5,%6,%7}, {%8,%9}, {%0,%1,%2,%3};" \
        : "+f"((d)[0]), "+f"((d)[1]), "+f"((d)[2]), "+f"((d)[3]) \
        : "r"((a)[0]), "r"((a)[1]), "r"((a)[2]), "r"((a)[3]), "r"((b)[0]), "r"((b)[1]))

__global__ void k_init() { g_loss = 0.f; g_reg = 0.f; }

__global__ void k_cvt_sq(const float* __restrict__ x) {
    int row  = (blockIdx.x * blockDim.x + threadIdx.x) >> 5;
    int lane = threadIdx.x & 31;
    float s = 0.f;
    #pragma unroll
    for (int q = 0; q < 4; ++q) {
        size_t i = (size_t)row * DD + lane * 4 + q * 128;
        float4 v = *(const float4*)(x + i);
        s = fmaf(v.x, v.x, s); s = fmaf(v.y, v.y, s);
        s = fmaf(v.z, v.z, s); s = fmaf(v.w, v.w, s);
        __nv_bfloat162 hA; hA.x = __float2bfloat16(v.x); hA.y = __float2bfloat16(v.y);
        __nv_bfloat162 hB; hB.x = __float2bfloat16(v.z); hB.y = __float2bfloat16(v.w);
        *(__nv_bfloat162*)(g_xhi + i)     = hA;
        *(__nv_bfloat162*)(g_xhi + i + 2) = hB;
    }
    #pragma unroll
    for (int off = 16; off; off >>= 1) s += __shfl_down_sync(0xffffffffu, s, off);
    if (lane == 0) g_sq[row] = s;
}

// ---------------- 3-stage cp.async mma.sync GEMM (hi only) + fused dual top-3 ----------------
__global__ __launch_bounds__(256, 2) void k_mma_top3() {
    extern __shared__ __align__(16) char dsm[];
    float* s_sqA = (float*)dsm;
    float* s_sqB = (float*)(dsm + 512);
    const unsigned BUF0 = 1024, BUFSZ = 20480, TILESZ = 10240;

    int t = threadIdx.x, lane = t & 31, wid = t >> 5;
    int wm = wid >> 1, wn = wid & 1;
    int mbase = wm * 32, nbase = wn * 64;

    int id = blockIdx.x, by = 0;
    while (id >= NT - by) { id -= NT - by; by++; }
    int bx = by + id;
    int rowA = by * 128, rowB = bx * 128;

    if (t < 128) { s_sqA[t] = g_sq[rowA + t]; s_sqB[t] = g_sq[rowB + t]; }

    unsigned sb = smem_u32(dsm);

    const char* srcPtr[4];
    unsigned dstOff[4];
    #pragma unroll
    for (int c = 0; c < 4; ++c) {
        int tile = c & 1, part = c >> 1;
        int i2 = t + 256 * part;
        int r = i2 >> 2, q = i2 & 3;
        int rowT = tile ? rowB : rowA;
        srcPtr[c] = (const char*)g_xhi + ((size_t)(rowT + r) << 10) + q * 16;
        dstOff[c] = BUF0 + tile * TILESZ + r * 80 + q * 16;
    }

    float acc[2][8][4];
    #pragma unroll
    for (int i = 0; i < 2; i++)
        #pragma unroll
        for (int j = 0; j < 8; j++)
            #pragma unroll
            for (int k = 0; k < 4; k++) acc[i][j][k] = 0.f;

    unsigned aOff = ((mbase + (lane & 15)) * 40 + (lane >> 4) * 8) * 2;
    unsigned bOff = ((nbase + (lane & 7) + ((lane >> 4) << 3)) * 40 + ((lane >> 3) & 1) * 8) * 2;

    #pragma unroll
    for (int c = 0; c < 4; ++c)
        asm volatile("cp.async.cg.shared.global [%0], [%1], 16;"
            :: "r"(sb + dstOff[c]), "l"(srcPtr[c]) : "memory");
    asm volatile("cp.async.commit_group;" ::: "memory");
    #pragma unroll
    for (int c = 0; c < 4; ++c)
        asm volatile("cp.async.cg.shared.global [%0], [%1], 16;"
            :: "r"(sb + dstOff[c] + BUFSZ), "l"(srcPtr[c] + 64) : "memory");
    asm volatile("cp.async.commit_group;" ::: "memory");

    for (int s = 0; s < 16; ++s) {
        if (s < 15) asm volatile("cp.async.wait_group 1;" ::: "memory");
        else        asm volatile("cp.async.wait_group 0;" ::: "memory");
        __syncthreads();

        if (s + 2 < 16) {
            unsigned bofs = ((s + 2) % 3) * BUFSZ;
            #pragma unroll
            for (int c = 0; c < 4; ++c)
                asm volatile("cp.async.cg.shared.global [%0], [%1], 16;"
                    :: "r"(sb + dstOff[c] + bofs), "l"(srcPtr[c] + (size_t)(s + 2) * 64) : "memory");
            asm volatile("cp.async.commit_group;" ::: "memory");
        }

        unsigned bb = sb + BUF0 + (s % 3) * BUFSZ;
        unsigned baseA = bb, baseB = bb + TILESZ;

        #pragma unroll
        for (int kh = 0; kh < 2; ++kh) {
            unsigned ko = kh * 32;
            unsigned aH[2][4], bb2[8][2];
            LDSMX4(aH[0][0], aH[0][1], aH[0][2], aH[0][3], baseA + aOff + ko);
            LDSMX4(aH[1][0], aH[1][1], aH[1][2], aH[1][3], baseA + aOff + 16 * 80 + ko);
            #pragma unroll
            for (int g = 0; g < 4; ++g)
                LDSMX4(bb2[2*g][0], bb2[2*g][1], bb2[2*g+1][0], bb2[2*g+1][1],
                       baseB + bOff + g * 16 * 80 + ko);
            #pragma unroll
            for (int mt = 0; mt < 2; ++mt)
                #pragma unroll
                for (int nt = 0; nt < 8; ++nt)
                    MMA16816(acc[mt][nt], aH[mt], bb2[nt]);
        }
    }
    __syncthreads();

    const float* sqa = s_sqA;
    const float* sqb = s_sqB;
    #pragma unroll
    for (int mt = 0; mt < 2; ++mt)
        #pragma unroll
        for (int nt = 0; nt < 8; ++nt)
            #pragma unroll
            for (int c4 = 0; c4 < 4; ++c4) {
                int h = c4 >> 1, c = c4 & 1;
                int ml = mbase + mt * 16 + (lane >> 2) + h * 8;
                int nl = nbase + nt * 8 + 2 * (lane & 3) + c;
                float d2 = sqa[ml] + sqb[nl] - 2.f * acc[mt][nt][c4];
                float e2 = d2 > 0.f ? d2 : 0.f;
                if (rowA + ml == rowB + nl) e2 = 0.f;
                acc[mt][nt][c4] = e2;
            }

    float* p_r = (float*)(dsm + BUF0);          // [128][2][3] = 3 KB
    float* p_c = (float*)(dsm + BUF0 + 4096);   // [128][4][3] = 6 KB

    // ---- row-direction top3 ----
    #pragma unroll
    for (int mt = 0; mt < 2; ++mt)
        #pragma unroll
        for (int h = 0; h < 2; ++h) {
            int ml = mbase + mt * 16 + (lane >> 2) + h * 8;
            float t0 = KEY_EMPTY, t1 = KEY_EMPTY, t2 = KEY_EMPTY;
            #pragma unroll
            for (int nt = 0; nt < 8; ++nt)
                #pragma unroll
                for (int c = 0; c < 2; ++c) {
                    int nl = nbase + nt * 8 + 2 * (lane & 3) + c;
                    ins3f(t0, t1, t2, packkey(acc[mt][nt][2 * h + c], (unsigned)(rowB + nl)));
                }
            #pragma unroll
            for (int off = 1; off <= 2; off <<= 1) {
                float r0 = __shfl_xor_sync(0xffffffffu, t0, off);
                float r1 = __shfl_xor_sync(0xffffffffu, t1, off);
                float r2 = __shfl_xor_sync(0xffffffffu, t2, off);
                ins3f(t0, t1, t2, r0); ins3f(t0, t1, t2, r1); ins3f(t0, t1, t2, r2);
            }
            if ((lane & 3) == 0) {
                int b = (ml * 2 + wn) * 3;
                p_r[b + 0] = t0; p_r[b + 1] = t1; p_r[b + 2] = t2;
            }
        }

    // ---- col-direction top3 ----
    if (bx != by) {
        #pragma unroll
        for (int nt = 0; nt < 8; ++nt)
            #pragma unroll
            for (int c = 0; c < 2; ++c) {
                int nl = nbase + nt * 8 + 2 * (lane & 3) + c;
                float t0 = KEY_EMPTY, t1 = KEY_EMPTY, t2 = KEY_EMPTY;
                #pragma unroll
                for (int mt = 0; mt < 2; ++mt)
                    #pragma unroll
                    for (int h = 0; h < 2; ++h) {
                        int ml = mbase + mt * 16 + (lane >> 2) + h * 8;
                        ins3f(t0, t1, t2, packkey(acc[mt][nt][2 * h + c], (unsigned)(rowA + ml)));
                    }
                #pragma unroll
                for (int off = 4; off <= 16; off <<= 1) {
                    float r0 = __shfl_xor_sync(0xffffffffu, t0, off);
                    float r1 = __shfl_xor_sync(0xffffffffu, t1, off);
                    float r2 = __shfl_xor_sync(0xffffffffu, t2, off);
                    ins3f(t0, t1, t2, r0); ins3f(t0, t1, t2, r1); ins3f(t0, t1, t2, r2);
                }
                if (lane < 4) {
                    int b = (nl * 4 + wm) * 3;
                    p_c[b + 0] = t0; p_c[b + 1] = t1; p_c[b + 2] = t2;
                }
            }
    }

    __syncthreads();
    if (t < 128) {
        float t0 = KEY_EMPTY, t1 = KEY_EMPTY, t2 = KEY_EMPTY;
        #pragma unroll
        for (int g = 0; g < 6; ++g) ins3f(t0, t1, t2, p_r[t * 6 + g]);
        size_t base = ((size_t)(rowA + t) * NT + bx) * 3;
        g_part[base + 0] = t0; g_part[base + 1] = t1; g_part[base + 2] = t2;
    } else if (bx != by) {
        int n = t - 128;
        float t0 = KEY_EMPTY, t1 = KEY_EMPTY, t2 = KEY_EMPTY;
        #pragma unroll
        for (int g = 0; g < 12; ++g) ins3f(t0, t1, t2, p_c[n * 12 + g]);
        size_t base = ((size_t)(rowB + n) * NT + by) * 3;
        g_part[base + 0] = t0; g_part[base + 1] = t1; g_part[base + 2] = t2;
    }
}

__global__ void k_merge() {
    int row  = (blockIdx.x * blockDim.x + threadIdx.x) >> 5;
    int lane = threadIdx.x & 31;
    float t0 = KEY_EMPTY, t1 = KEY_EMPTY, t2 = KEY_EMPTY;
    size_t base = (size_t)row * (NT * 3);
    for (int p = lane; p < NT * 3; p += 32) ins3f(t0, t1, t2, g_part[base + p]);
    #pragma unroll
    for (int off = 16; off; off >>= 1) {
        float r0 = __shfl_down_sync(0xffffffffu, t0, off);
        float r1 = __shfl_down_sync(0xffffffffu, t1, off);
        float r2 = __shfl_down_sync(0xffffffffu, t2, off);
        ins3f(t0, t1, t2, r0); ins3f(t0, t1, t2, r1); ins3f(t0, t1, t2, r2);
    }
    if (lane == 0) {
        g_top3[(size_t)row * 3 + 0] = t0;
        g_top3[(size_t)row * 3 + 1] = t1;
        g_top3[(size_t)row * 3 + 2] = t2;
    }
}

// Cross-entropy: 256 threads = 128 cols x 2 K-halves; 16 rows/block.
__global__ __launch_bounds__(256) void k_loss(const float* __restrict__ x,
                                              const int* __restrict__ y,
                                              const float* __restrict__ W,
                                              const float* __restrict__ b) {
    __shared__ float xs[16][512];
    __shared__ float lgp[16][128];
    __shared__ float lg[16][128];
    int tid  = threadIdx.x;
    int row0 = blockIdx.x * 16;
    int c = tid & 127;
    int half = tid >> 7;

    #pragma unroll
    for (int i = 0; i < 8; ++i) {
        int id = tid + 256 * i;
        int r  = id >> 7;
        int q  = id & 127;
        float4 v = *(const float4*)&x[(size_t)(row0 + r) * DD + q * 4];
        *(float4*)&xs[r][q * 4] = v;
    }
    __syncthreads();

    float acc[16];
    #pragma unroll
    for (int r = 0; r < 16; r++) acc[r] = 0.f;
    int kbase = half * 256;
    #pragma unroll 4
    for (int d0 = 0; d0 < 256; d0 += 4) {
        int d = kbase + d0;
        float w0 = W[(d + 0) * CC + c];
        float w1 = W[(d + 1) * CC + c];
        float w2 = W[(d + 2) * CC + c];
        float w3 = W[(d + 3) * CC + c];
        #pragma unroll
        for (int r = 0; r < 16; r++) {
            float4 xv = *(const float4*)&xs[r][d];
            acc[r] = fmaf(xv.x, w0, acc[r]);
            acc[r] = fmaf(xv.y, w1, acc[r]);
            acc[r] = fmaf(xv.z, w2, acc[r]);
            acc[r] = fmaf(xv.w, w3, acc[r]);
        }
    }
    if (half == 1) {
        #pragma unroll
        for (int r = 0; r < 16; r++) lgp[r][c] = acc[r];
    }
    __syncthreads();
    if (half == 0) {
        float bc = b[c];
        #pragma unroll
        for (int r = 0; r < 16; r++) lg[r][c] = acc[r] + lgp[r][c] + bc;
    }
    __syncthreads();

    int w = tid >> 5, lane = tid & 31;
    #pragma unroll
    for (int s = 0; s < 2; ++s) {
        int r = w * 2 + s;
        float l0 = lg[r][lane], l1 = lg[r][lane + 32], l2 = lg[r][lane + 64], l3 = lg[r][lane + 96];
        float mx = fmaxf(fmaxf(l0, l1), fmaxf(l2, l3));
        #pragma unroll
        for (int off = 16; off; off >>= 1) mx = fmaxf(mx, __shfl_xor_sync(0xffffffffu, mx, off));
        float se = expf(l0 - mx) + expf(l1 - mx) + expf(l2 - mx) + expf(l3 - mx);
        #pragma unroll
        for (int off = 16; off; off >>= 1) se += __shfl_xor_sync(0xffffffffu, se, off);
        if (lane == 0) {
            int lab  = y[row0 + r];
            float ll = lg[r][lab];
            atomicAdd(&g_loss, (mx + logf(se) - ll) * (1.0f / NN));
        }
    }
}

__global__ void k_reg(const int* __restrict__ y, const float* __restrict__ yo) {
    int row  = (blockIdx.x * blockDim.x + threadIdx.x) >> 5;
    int lane = threadIdx.x & 31;
    unsigned b0 = __float_as_uint(g_top3[(size_t)row * 3 + 0]);
    unsigned b1 = __float_as_uint(g_top3[(size_t)row * 3 + 1]);
    unsigned b2 = __float_as_uint(g_top3[(size_t)row * 3 + 2]);
    int yi = y[row];
    float acc = 0.f;
    #pragma unroll
    for (int tq = 0; tq < 3; ++tq) {
        unsigned bt = (tq == 0) ? b0 : (tq == 1) ? b1 : b2;
        int n = (int)(bt & 0xFFFu);
        float e2;
        bool use = true;
        if      (n == 0) e2 = __uint_as_float(b0 & 0xFFFFF000u);
        else if (n == 1) e2 = __uint_as_float(b1 & 0xFFFFF000u);
        else if (n == 2) e2 = __uint_as_float(b2 & 0xFFFFF000u);
        else { e2 = 0.f; use = false; }  // exp(-d_sorted[i, n>=3]) <= ~2e-12: drop
        if (!use) continue;
        if (y[n] != yi) continue;
        float s = 0.f;
        #pragma unroll
        for (int q = 0; q < 4; ++q) {
            float dv = yo[(size_t)row * CC + lane + 32 * q] - yo[(size_t)n * CC + lane + 32 * q];
            s = fmaf(dv, dv, s);
        }
        #pragma unroll
        for (int off = 16; off; off >>= 1) s += __shfl_xor_sync(0xffffffffu, s, off);
        float dyv = sqrtf(s);
        acc += dyv * expf(-sqrtf(e2));
    }
    if (lane == 0) atomicAdd(&g_reg, acc);
}

__global__ void k_final(float* out) { out[0] = g_loss + ALPHA_ * g_reg; }

extern "C" void kernel_launch(void* const* d_in, const int* in_sizes, int n_in,
                              void* d_out, int out_size) {
    (void)in_sizes; (void)n_in; (void)out_size;
    const float* x  = (const float*)d_in[0];
    const int*   y  = (const int*)d_in[1];
    const float* yo = (const float*)d_in[2];
    const float* W  = (const float*)d_in[3];
    const float* b  = (const float*)d_in[4];
    float* out = (float*)d_out;

    const int DYN_SMEM = 1024 + 3 * 20480;   // 62464
    cudaFuncSetAttribute(k_mma_top3, cudaFuncAttributeMaxDynamicSharedMemorySize, DYN_SMEM);

    k_init<<<1, 1>>>();
    k_cvt_sq<<<NN / 8, 256>>>(x);
    k_loss<<<NN / 16, 256>>>(x, y, W, b);
    k_mma_top3<<<NT * (NT + 1) / 2, 256, DYN_SMEM>>>();
    k_merge<<<NN / 8, 256>>>();
    k_reg<<<NN / 8, 256>>>(y, yo);
    k_final<<<1, 1>>>(out);
}